// round 3
// baseline (speedup 1.0000x reference)
#include <cuda_runtime.h>
#include <cuda_bf16.h>
#include <math.h>

// Problem constants
#define B_  4
#define S_  2048
#define D_  1024
#define H_  16
#define DH_ 64
#define M_  (B_ * S_)

// Scratch for projected Q, K, V in [B, H, S, Dh] layout (fp32)
__device__ float g_Q[B_ * H_ * S_ * DH_];
__device__ float g_K[B_ * H_ * S_ * DH_];
__device__ float g_V[B_ * H_ * S_ * DH_];

// ---------------------------------------------------------------------------
// Helpers: tf32 convert + m16n8k8 tf32 mma
// ---------------------------------------------------------------------------
__device__ __forceinline__ unsigned f2tf(float f) {
    unsigned u;
    asm("cvt.rna.tf32.f32 %0, %1;" : "=r"(u) : "f"(f));
    return u;
}

__device__ __forceinline__ void mma_tf32(float c[4],
                                         unsigned a0, unsigned a1, unsigned a2, unsigned a3,
                                         unsigned b0, unsigned b1) {
    asm volatile(
        "mma.sync.aligned.m16n8k8.row.col.f32.tf32.tf32.f32 "
        "{%0,%1,%2,%3}, {%4,%5,%6,%7}, {%8,%9}, {%0,%1,%2,%3};"
        : "+f"(c[0]), "+f"(c[1]), "+f"(c[2]), "+f"(c[3])
        : "r"(a0), "r"(a1), "r"(a2), "r"(a3), "r"(b0), "r"(b1));
}

// ---------------------------------------------------------------------------
// Kernel 1: QKV projection GEMM on tensor cores (tf32), double-buffered smem.
// BM=128, BN=128, BK=16; 8 warps (2x4); warp tile 64x32; m16n8k8 mma.
// ---------------------------------------------------------------------------
#define AS_STRIDE 20
#define BS_STRIDE 136

__global__ __launch_bounds__(256)
void qkv_gemm_tc(const float* __restrict__ X,
                 const float* __restrict__ Wq, const float* __restrict__ bq,
                 const float* __restrict__ Wk, const float* __restrict__ bk,
                 const float* __restrict__ Wv, const float* __restrict__ bv)
{
    __shared__ unsigned As[2][128 * AS_STRIDE];
    __shared__ unsigned Bs[2][16 * BS_STRIDE];

    const int tid  = threadIdx.x;
    const int lane = tid & 31;
    const int wrp  = tid >> 5;        // 0..7
    const int g    = lane >> 2;       // 0..7
    const int t    = lane & 3;        // 0..3
    const int wm   = wrp >> 2;        // 0..1
    const int wn   = wrp & 3;         // 0..3

    const int m0 = blockIdx.y * 128;
    const int n0 = blockIdx.x * 128;
    const int z  = blockIdx.z;

    const float* W    = (z == 0) ? Wq : (z == 1) ? Wk : Wv;
    const float* bias = (z == 0) ? bq : (z == 1) ? bk : bv;
    float* dst        = (z == 0) ? g_Q : (z == 1) ? g_K : g_V;

    float acc[4][4][4];
    #pragma unroll
    for (int i = 0; i < 4; i++)
        #pragma unroll
        for (int j = 0; j < 4; j++)
            #pragma unroll
            for (int r = 0; r < 4; r++) acc[i][j][r] = 0.0f;

    int a_row[2], a_c[2], b_row[2], b_c[2];
    #pragma unroll
    for (int it = 0; it < 2; it++) {
        const int idx = tid + it * 256;
        a_row[it] = idx >> 2;  a_c[it] = (idx & 3) << 2;
        b_row[it] = idx >> 5;  b_c[it] = (idx & 31) << 2;
    }

    float4 ra[2], rb[2];
    #pragma unroll
    for (int it = 0; it < 2; it++) {
        ra[it] = *reinterpret_cast<const float4*>(
            &X[(size_t)(m0 + a_row[it]) * D_ + a_c[it]]);
        rb[it] = *reinterpret_cast<const float4*>(
            &W[(size_t)b_row[it] * D_ + n0 + b_c[it]]);
    }

    int buf = 0;
    for (int kt = 0; kt < D_ / 16; kt++) {
        // store staged tile (cvt to tf32)
        #pragma unroll
        for (int it = 0; it < 2; it++) {
            unsigned* ap = &As[buf][a_row[it] * AS_STRIDE + a_c[it]];
            ap[0] = f2tf(ra[it].x); ap[1] = f2tf(ra[it].y);
            ap[2] = f2tf(ra[it].z); ap[3] = f2tf(ra[it].w);
            unsigned* bp = &Bs[buf][b_row[it] * BS_STRIDE + b_c[it]];
            bp[0] = f2tf(rb[it].x); bp[1] = f2tf(rb[it].y);
            bp[2] = f2tf(rb[it].z); bp[3] = f2tf(rb[it].w);
        }
        __syncthreads();

        // prefetch next tile (in flight during compute)
        if (kt + 1 < D_ / 16) {
            const int koff = (kt + 1) * 16;
            #pragma unroll
            for (int it = 0; it < 2; it++) {
                ra[it] = *reinterpret_cast<const float4*>(
                    &X[(size_t)(m0 + a_row[it]) * D_ + koff + a_c[it]]);
                rb[it] = *reinterpret_cast<const float4*>(
                    &W[(size_t)(koff + b_row[it]) * D_ + n0 + b_c[it]]);
            }
        }

        #pragma unroll
        for (int ks = 0; ks < 16; ks += 8) {
            unsigned af[4][4];
            #pragma unroll
            for (int i = 0; i < 4; i++) {
                const int rbase = (wm * 64 + i * 16 + g) * AS_STRIDE + ks + t;
                af[i][0] = As[buf][rbase];
                af[i][1] = As[buf][rbase + 8 * AS_STRIDE];
                af[i][2] = As[buf][rbase + 4];
                af[i][3] = As[buf][rbase + 8 * AS_STRIDE + 4];
            }
            unsigned bf[4][2];
            #pragma unroll
            for (int j = 0; j < 4; j++) {
                const int bbase = (ks + t) * BS_STRIDE + wn * 32 + j * 8 + g;
                bf[j][0] = Bs[buf][bbase];
                bf[j][1] = Bs[buf][bbase + 4 * BS_STRIDE];
            }
            #pragma unroll
            for (int i = 0; i < 4; i++)
                #pragma unroll
                for (int j = 0; j < 4; j++)
                    mma_tf32(acc[i][j], af[i][0], af[i][1], af[i][2], af[i][3],
                             bf[j][0], bf[j][1]);
        }
        buf ^= 1;   // next store goes to the other buffer; no tail barrier needed
    }

    // Epilogue: bias + scatter into [B, H, S, Dh]
    #pragma unroll
    for (int i = 0; i < 4; i++) {
        const int mrow0 = m0 + wm * 64 + i * 16 + g;
        const int mrow1 = mrow0 + 8;
        #pragma unroll
        for (int j = 0; j < 4; j++) {
            const int n = n0 + wn * 32 + j * 8 + 2 * t;
            const int h = n >> 6;
            const int d = n & 63;
            const float b0v = bias[n], b1v = bias[n + 1];
            {
                const int bb = mrow0 >> 11, s = mrow0 & 2047;
                float2 v = make_float2(acc[i][j][0] + b0v, acc[i][j][1] + b1v);
                *reinterpret_cast<float2*>(
                    &dst[(((size_t)(bb * H_ + h)) * S_ + s) * DH_ + d]) = v;
            }
            {
                const int bb = mrow1 >> 11, s = mrow1 & 2047;
                float2 v = make_float2(acc[i][j][2] + b0v, acc[i][j][3] + b1v);
                *reinterpret_cast<float2*>(
                    &dst[(((size_t)(bb * H_ + h)) * S_ + s) * DH_ + d]) = v;
            }
        }
    }
}

// ---------------------------------------------------------------------------
// Kernel 2: flash attention on tensor cores (tf32), double-buffered K/V.
// Block = 256 threads (8 warps), Q tile 128 rows, K/V tiles 64 rows.
// Warp w owns query rows [w*16, w*16+16). Q fragments in registers.
// smem (u32): Ks[2][64*68] | Vs[2][64*72] | Ps[128*68]
// ---------------------------------------------------------------------------
#define KS_STRIDE 68
#define VS_STRIDE 72
#define PS_STRIDE 68
#define ATTN_SMEM_U32 (2 * 64 * KS_STRIDE + 2 * 64 * VS_STRIDE + 128 * PS_STRIDE)

__global__ __launch_bounds__(256)
void attn_tc(float* __restrict__ out)
{
    extern __shared__ unsigned sm_u[];
    unsigned* Ks0 = sm_u;
    unsigned* Ks1 = Ks0 + 64 * KS_STRIDE;
    unsigned* Vs0 = Ks1 + 64 * KS_STRIDE;
    unsigned* Vs1 = Vs0 + 64 * VS_STRIDE;
    unsigned* Ps  = Vs1 + 64 * VS_STRIDE;

    const int tid  = threadIdx.x;
    const int lane = tid & 31;
    const int wrp  = tid >> 5;
    const int g    = lane >> 2;
    const int t    = lane & 3;

    const int qt = blockIdx.x;
    const int h  = blockIdx.y;
    const int b  = blockIdx.z;

    const size_t head_base = ((size_t)(b * H_ + h)) * S_ * DH_;
    const float* Qg = g_Q + head_base + (size_t)qt * 128 * DH_;
    const float* Kg = g_K + head_base;
    const float* Vg = g_V + head_base;

    // per-thread staging coords: 4 float4 of K + 4 of V per tile
    int kv_r[4], kv_c[4];
    #pragma unroll
    for (int it = 0; it < 4; it++) {
        const int idx = tid + it * 256;
        kv_r[it] = idx >> 4;
        kv_c[it] = (idx & 15) << 2;
    }

    // issue tile-0 K/V loads first (overlap with Q staging below)
    float4 rk[4], rv[4];
    #pragma unroll
    for (int it = 0; it < 4; it++) {
        rk[it] = *reinterpret_cast<const float4*>(&Kg[(size_t)kv_r[it] * DH_ + kv_c[it]]);
        rv[it] = *reinterpret_cast<const float4*>(&Vg[(size_t)kv_r[it] * DH_ + kv_c[it]]);
    }

    // Stage Q (128x64) into Ps, cvt tf32
    #pragma unroll
    for (int it = 0; it < 8; it++) {
        const int idx = tid + it * 256;
        const int r = idx >> 4;
        const int c = (idx & 15) << 2;
        float4 qv = *reinterpret_cast<const float4*>(&Qg[(size_t)r * DH_ + c]);
        unsigned* p = &Ps[r * PS_STRIDE + c];
        p[0] = f2tf(qv.x); p[1] = f2tf(qv.y); p[2] = f2tf(qv.z); p[3] = f2tf(qv.w);
    }
    __syncthreads();

    // Load Q fragments (8 k-steps over d=64)
    unsigned qf[8][4];
    #pragma unroll
    for (int kk = 0; kk < 8; kk++) {
        const int base = (wrp * 16 + g) * PS_STRIDE + kk * 8 + t;
        qf[kk][0] = Ps[base];
        qf[kk][1] = Ps[base + 8 * PS_STRIDE];
        qf[kk][2] = Ps[base + 4];
        qf[kk][3] = Ps[base + 8 * PS_STRIDE + 4];
    }

    float oacc[8][4];
    #pragma unroll
    for (int j = 0; j < 8; j++)
        #pragma unroll
        for (int r = 0; r < 4; r++) oacc[j][r] = 0.0f;
    float m0 = -INFINITY, m1 = -INFINITY, l0 = 0.0f, l1 = 0.0f;

    for (int kt = 0; kt < S_ / 64; kt++) {
        unsigned* Ksb = (kt & 1) ? Ks1 : Ks0;
        unsigned* Vsb = (kt & 1) ? Vs1 : Vs0;

        // store staged K/V (cvt to tf32)
        #pragma unroll
        for (int it = 0; it < 4; it++) {
            unsigned* kp = &Ksb[kv_r[it] * KS_STRIDE + kv_c[it]];
            kp[0] = f2tf(rk[it].x); kp[1] = f2tf(rk[it].y);
            kp[2] = f2tf(rk[it].z); kp[3] = f2tf(rk[it].w);
            unsigned* vp = &Vsb[kv_r[it] * VS_STRIDE + kv_c[it]];
            vp[0] = f2tf(rv[it].x); vp[1] = f2tf(rv[it].y);
            vp[2] = f2tf(rv[it].z); vp[3] = f2tf(rv[it].w);
        }
        __syncthreads();   // single barrier per tile (double-buffered)

        // prefetch next K/V tile — LDGs in flight during 128 MMAs below
        if (kt + 1 < S_ / 64) {
            const size_t roff = (size_t)(kt + 1) * 64;
            #pragma unroll
            for (int it = 0; it < 4; it++) {
                rk[it] = *reinterpret_cast<const float4*>(
                    &Kg[(roff + kv_r[it]) * DH_ + kv_c[it]]);
                rv[it] = *reinterpret_cast<const float4*>(
                    &Vg[(roff + kv_r[it]) * DH_ + kv_c[it]]);
            }
        }

        // S = Q @ K^T (warp: m16 x n64, k=64)
        float sacc[8][4];
        #pragma unroll
        for (int j = 0; j < 8; j++)
            #pragma unroll
            for (int r = 0; r < 4; r++) sacc[j][r] = 0.0f;

        #pragma unroll
        for (int kk = 0; kk < 8; kk++) {
            #pragma unroll
            for (int j = 0; j < 8; j++) {
                const int bbase = (j * 8 + g) * KS_STRIDE + kk * 8 + t;
                mma_tf32(sacc[j], qf[kk][0], qf[kk][1], qf[kk][2], qf[kk][3],
                         Ksb[bbase], Ksb[bbase + 4]);
            }
        }

        // scale + online softmax (rows g and g+8 of this warp's m16)
        const float scale = 0.125f;
        float mx0 = -INFINITY, mx1 = -INFINITY;
        #pragma unroll
        for (int j = 0; j < 8; j++) {
            sacc[j][0] *= scale; sacc[j][1] *= scale;
            sacc[j][2] *= scale; sacc[j][3] *= scale;
            mx0 = fmaxf(mx0, fmaxf(sacc[j][0], sacc[j][1]));
            mx1 = fmaxf(mx1, fmaxf(sacc[j][2], sacc[j][3]));
        }
        #pragma unroll
        for (int off = 1; off <= 2; off <<= 1) {
            mx0 = fmaxf(mx0, __shfl_xor_sync(0xffffffffu, mx0, off));
            mx1 = fmaxf(mx1, __shfl_xor_sync(0xffffffffu, mx1, off));
        }
        const float mn0 = fmaxf(m0, mx0);
        const float mn1 = fmaxf(m1, mx1);
        const float corr0 = __expf(m0 - mn0);
        const float corr1 = __expf(m1 - mn1);
        m0 = mn0; m1 = mn1;

        float sum0 = 0.0f, sum1 = 0.0f;
        #pragma unroll
        for (int j = 0; j < 8; j++) {
            sacc[j][0] = __expf(sacc[j][0] - mn0);
            sacc[j][1] = __expf(sacc[j][1] - mn0);
            sacc[j][2] = __expf(sacc[j][2] - mn1);
            sacc[j][3] = __expf(sacc[j][3] - mn1);
            sum0 += sacc[j][0] + sacc[j][1];
            sum1 += sacc[j][2] + sacc[j][3];
        }
        #pragma unroll
        for (int off = 1; off <= 2; off <<= 1) {
            sum0 += __shfl_xor_sync(0xffffffffu, sum0, off);
            sum1 += __shfl_xor_sync(0xffffffffu, sum1, off);
        }
        l0 = l0 * corr0 + sum0;
        l1 = l1 * corr1 + sum1;

        #pragma unroll
        for (int j = 0; j < 8; j++) {
            oacc[j][0] *= corr0; oacc[j][1] *= corr0;
            oacc[j][2] *= corr1; oacc[j][3] *= corr1;
        }

        // store P (tf32) into Ps — warp-local rows only
        #pragma unroll
        for (int j = 0; j < 8; j++) {
            const int base = (wrp * 16 + g) * PS_STRIDE + j * 8 + 2 * t;
            Ps[base]     = f2tf(sacc[j][0]);
            Ps[base + 1] = f2tf(sacc[j][1]);
            Ps[base + 8 * PS_STRIDE]     = f2tf(sacc[j][2]);
            Ps[base + 8 * PS_STRIDE + 1] = f2tf(sacc[j][3]);
        }
        __syncwarp();

        // O += P @ V
        #pragma unroll
        for (int kk = 0; kk < 8; kk++) {
            const int abase = (wrp * 16 + g) * PS_STRIDE + kk * 8 + t;
            const unsigned a0 = Ps[abase];
            const unsigned a1 = Ps[abase + 8 * PS_STRIDE];
            const unsigned a2 = Ps[abase + 4];
            const unsigned a3 = Ps[abase + 8 * PS_STRIDE + 4];
            #pragma unroll
            for (int j = 0; j < 8; j++) {
                const int vb = (kk * 8 + t) * VS_STRIDE + j * 8 + g;
                mma_tf32(oacc[j], a0, a1, a2, a3, Vsb[vb], Vsb[vb + 4 * VS_STRIDE]);
            }
        }
    }

    // Final: normalize + store [B, S, D]
    const float inv0 = 1.0f / l0;
    const float inv1 = 1.0f / l1;
    const int row0 = qt * 128 + wrp * 16 + g;
    const int row1 = row0 + 8;
    const size_t o0 = ((size_t)(b * S_ + row0)) * D_ + h * DH_;
    const size_t o1 = ((size_t)(b * S_ + row1)) * D_ + h * DH_;
    #pragma unroll
    for (int j = 0; j < 8; j++) {
        const int d = j * 8 + 2 * t;
        *reinterpret_cast<float2*>(&out[o0 + d]) =
            make_float2(oacc[j][0] * inv0, oacc[j][1] * inv0);
        *reinterpret_cast<float2*>(&out[o1 + d]) =
            make_float2(oacc[j][2] * inv1, oacc[j][3] * inv1);
    }
}

// ---------------------------------------------------------------------------
extern "C" void kernel_launch(void* const* d_in, const int* in_sizes, int n_in,
                              void* d_out, int out_size)
{
    const float* x  = (const float*)d_in[0];
    const float* Wq = (const float*)d_in[1];
    const float* bq = (const float*)d_in[2];
    const float* Wk = (const float*)d_in[3];
    const float* bk = (const float*)d_in[4];
    const float* Wv = (const float*)d_in[5];
    const float* bv = (const float*)d_in[6];
    float* out = (float*)d_out;

    dim3 g1(D_ / 128, M_ / 128, 3);
    qkv_gemm_tc<<<g1, 256>>>(x, Wq, bq, Wk, bk, Wv, bv);

    const int smem_bytes = ATTN_SMEM_U32 * sizeof(unsigned);
    cudaFuncSetAttribute(attn_tc,
                         cudaFuncAttributeMaxDynamicSharedMemorySize, smem_bytes);
    dim3 g2(S_ / 128, H_, B_);
    attn_tc<<<g2, 256, smem_bytes>>>(out);
}

// round 4
// speedup vs baseline: 1.3378x; 1.3378x over previous
#include <cuda_runtime.h>
#include <cuda_bf16.h>
#include <math.h>

// Problem constants
#define B_  4
#define S_  2048
#define D_  1024
#define H_  16
#define DH_ 64
#define M_  (B_ * S_)

// Scratch for projected Q, K, V in [B, H, S, Dh] layout (fp32)
__device__ float g_Q[B_ * H_ * S_ * DH_];
__device__ float g_K[B_ * H_ * S_ * DH_];
__device__ float g_V[B_ * H_ * S_ * DH_];

// ---------------------------------------------------------------------------
// Helpers
// ---------------------------------------------------------------------------
__device__ __forceinline__ unsigned f2tf(float f) {
    unsigned u;
    asm("cvt.rna.tf32.f32 %0, %1;" : "=r"(u) : "f"(f));
    return u;
}

__device__ __forceinline__ void mma_tf32(float c[4],
                                         unsigned a0, unsigned a1, unsigned a2, unsigned a3,
                                         unsigned b0, unsigned b1) {
    asm volatile(
        "mma.sync.aligned.m16n8k8.row.col.f32.tf32.tf32.f32 "
        "{%0,%1,%2,%3}, {%4,%5,%6,%7}, {%8,%9}, {%0,%1,%2,%3};"
        : "+f"(c[0]), "+f"(c[1]), "+f"(c[2]), "+f"(c[3])
        : "r"(a0), "r"(a1), "r"(a2), "r"(a3), "r"(b0), "r"(b1));
}

__device__ __forceinline__ unsigned smem_u32(const void* p) {
    unsigned a;
    asm("{ .reg .u64 t; cvta.to.shared.u64 t, %1; cvt.u32.u64 %0, t; }"
        : "=r"(a) : "l"(p));
    return a;
}

__device__ __forceinline__ void cp_async16(unsigned saddr, const void* gptr) {
    asm volatile("cp.async.cg.shared.global [%0], [%1], 16;"
                 :: "r"(saddr), "l"(gptr));
}
__device__ __forceinline__ void cp_commit() {
    asm volatile("cp.async.commit_group;");
}
__device__ __forceinline__ void cp_wait_all() {
    asm volatile("cp.async.wait_group 0;");
}

// ---------------------------------------------------------------------------
// Kernel 1: QKV projection GEMM (tf32 mma), R2 structure (single buffer).
// BM=128, BN=128, BK=16; 8 warps (2x4); warp tile 64x32.
// ---------------------------------------------------------------------------
#define AS_STRIDE 20
#define BS_STRIDE 136

__global__ __launch_bounds__(256)
void qkv_gemm_tc(const float* __restrict__ X,
                 const float* __restrict__ Wq, const float* __restrict__ bq,
                 const float* __restrict__ Wk, const float* __restrict__ bk,
                 const float* __restrict__ Wv, const float* __restrict__ bv)
{
    __shared__ unsigned As[128 * AS_STRIDE];
    __shared__ unsigned Bs[16 * BS_STRIDE];

    const int tid  = threadIdx.x;
    const int lane = tid & 31;
    const int wrp  = tid >> 5;
    const int g    = lane >> 2;
    const int t    = lane & 3;
    const int wm   = wrp >> 2;
    const int wn   = wrp & 3;

    const int m0 = blockIdx.y * 128;
    const int n0 = blockIdx.x * 128;
    const int z  = blockIdx.z;

    const float* W    = (z == 0) ? Wq : (z == 1) ? Wk : Wv;
    const float* bias = (z == 0) ? bq : (z == 1) ? bk : bv;
    float* dst        = (z == 0) ? g_Q : (z == 1) ? g_K : g_V;

    float acc[4][4][4];
    #pragma unroll
    for (int i = 0; i < 4; i++)
        #pragma unroll
        for (int j = 0; j < 4; j++)
            #pragma unroll
            for (int r = 0; r < 4; r++) acc[i][j][r] = 0.0f;

    int a_row[2], a_c[2], b_row[2], b_c[2];
    #pragma unroll
    for (int it = 0; it < 2; it++) {
        const int idx = tid + it * 256;
        a_row[it] = idx >> 2;  a_c[it] = (idx & 3) << 2;
        b_row[it] = idx >> 5;  b_c[it] = (idx & 31) << 2;
    }

    float4 ra[2], rb[2];
    #pragma unroll
    for (int it = 0; it < 2; it++) {
        ra[it] = *reinterpret_cast<const float4*>(
            &X[(size_t)(m0 + a_row[it]) * D_ + a_c[it]]);
        rb[it] = *reinterpret_cast<const float4*>(
            &W[(size_t)b_row[it] * D_ + n0 + b_c[it]]);
    }

    for (int kt = 0; kt < D_ / 16; kt++) {
        #pragma unroll
        for (int it = 0; it < 2; it++) {
            unsigned* ap = &As[a_row[it] * AS_STRIDE + a_c[it]];
            ap[0] = f2tf(ra[it].x); ap[1] = f2tf(ra[it].y);
            ap[2] = f2tf(ra[it].z); ap[3] = f2tf(ra[it].w);
            unsigned* bp = &Bs[b_row[it] * BS_STRIDE + b_c[it]];
            bp[0] = f2tf(rb[it].x); bp[1] = f2tf(rb[it].y);
            bp[2] = f2tf(rb[it].z); bp[3] = f2tf(rb[it].w);
        }
        __syncthreads();

        if (kt + 1 < D_ / 16) {
            const int koff = (kt + 1) * 16;
            #pragma unroll
            for (int it = 0; it < 2; it++) {
                ra[it] = *reinterpret_cast<const float4*>(
                    &X[(size_t)(m0 + a_row[it]) * D_ + koff + a_c[it]]);
                rb[it] = *reinterpret_cast<const float4*>(
                    &W[(size_t)(koff + b_row[it]) * D_ + n0 + b_c[it]]);
            }
        }

        #pragma unroll
        for (int ks = 0; ks < 16; ks += 8) {
            unsigned af[4][4];
            #pragma unroll
            for (int i = 0; i < 4; i++) {
                const int rbase = (wm * 64 + i * 16 + g) * AS_STRIDE + ks + t;
                af[i][0] = As[rbase];
                af[i][1] = As[rbase + 8 * AS_STRIDE];
                af[i][2] = As[rbase + 4];
                af[i][3] = As[rbase + 8 * AS_STRIDE + 4];
            }
            unsigned bf[4][2];
            #pragma unroll
            for (int j = 0; j < 4; j++) {
                const int bbase = (ks + t) * BS_STRIDE + wn * 32 + j * 8 + g;
                bf[j][0] = Bs[bbase];
                bf[j][1] = Bs[bbase + 4 * BS_STRIDE];
            }
            #pragma unroll
            for (int i = 0; i < 4; i++)
                #pragma unroll
                for (int j = 0; j < 4; j++)
                    mma_tf32(acc[i][j], af[i][0], af[i][1], af[i][2], af[i][3],
                             bf[j][0], bf[j][1]);
        }
        __syncthreads();
    }

    #pragma unroll
    for (int i = 0; i < 4; i++) {
        const int mrow0 = m0 + wm * 64 + i * 16 + g;
        const int mrow1 = mrow0 + 8;
        #pragma unroll
        for (int j = 0; j < 4; j++) {
            const int n = n0 + wn * 32 + j * 8 + 2 * t;
            const int h = n >> 6;
            const int d = n & 63;
            const float b0v = bias[n], b1v = bias[n + 1];
            {
                const int bb = mrow0 >> 11, s = mrow0 & 2047;
                float2 v = make_float2(acc[i][j][0] + b0v, acc[i][j][1] + b1v);
                *reinterpret_cast<float2*>(
                    &dst[(((size_t)(bb * H_ + h)) * S_ + s) * DH_ + d]) = v;
            }
            {
                const int bb = mrow1 >> 11, s = mrow1 & 2047;
                float2 v = make_float2(acc[i][j][2] + b0v, acc[i][j][3] + b1v);
                *reinterpret_cast<float2*>(
                    &dst[(((size_t)(bb * H_ + h)) * S_ + s) * DH_ + d]) = v;
            }
        }
    }
}

// ---------------------------------------------------------------------------
// Kernel 2: flash attention (tf32 mma), cp.async double-buffered K/V.
// Block = 256 threads (8 warps), Q tile 128 rows, K/V tiles 64 rows.
// K/V stored in smem as RAW fp32 (HW truncates to tf32 at the MMA).
// smem (u32): Ks[2][64*68] | Vs[2][64*72] | Ps[128*68]
// ---------------------------------------------------------------------------
#define KS_STRIDE 68
#define VS_STRIDE 72
#define PS_STRIDE 68
#define ATTN_SMEM_U32 (2 * 64 * KS_STRIDE + 2 * 64 * VS_STRIDE + 128 * PS_STRIDE)

__global__ __launch_bounds__(256)
void attn_tc(float* __restrict__ out)
{
    extern __shared__ unsigned sm_u[];
    unsigned* Ksb_[2] = { sm_u, sm_u + 64 * KS_STRIDE };
    unsigned* Vsb_[2] = { sm_u + 2 * 64 * KS_STRIDE,
                          sm_u + 2 * 64 * KS_STRIDE + 64 * VS_STRIDE };
    unsigned* Ps = sm_u + 2 * 64 * KS_STRIDE + 2 * 64 * VS_STRIDE;

    const int tid  = threadIdx.x;
    const int lane = tid & 31;
    const int wrp  = tid >> 5;
    const int g    = lane >> 2;
    const int t    = lane & 3;

    const int qt = blockIdx.x;
    const int h  = blockIdx.y;
    const int b  = blockIdx.z;

    const size_t head_base = ((size_t)(b * H_ + h)) * S_ * DH_;
    const float* Qg = g_Q + head_base + (size_t)qt * 128 * DH_;
    const float* Kg = g_K + head_base;
    const float* Vg = g_V + head_base;

    // per-thread staging coords: 4 float4 of K + 4 of V per tile
    int kv_r[4], kv_c[4];
    #pragma unroll
    for (int it = 0; it < 4; it++) {
        const int idx = tid + it * 256;
        kv_r[it] = idx >> 4;
        kv_c[it] = (idx & 15) << 2;
    }

    // issue tile-0 K/V cp.asyncs (in flight during Q staging)
    #pragma unroll
    for (int it = 0; it < 4; it++) {
        cp_async16(smem_u32(&Ksb_[0][kv_r[it] * KS_STRIDE + kv_c[it]]),
                   &Kg[(size_t)kv_r[it] * DH_ + kv_c[it]]);
        cp_async16(smem_u32(&Vsb_[0][kv_r[it] * VS_STRIDE + kv_c[it]]),
                   &Vg[(size_t)kv_r[it] * DH_ + kv_c[it]]);
    }
    cp_commit();

    // Stage Q (128x64) into Ps, cvt tf32
    #pragma unroll
    for (int it = 0; it < 8; it++) {
        const int idx = tid + it * 256;
        const int r = idx >> 4;
        const int c = (idx & 15) << 2;
        float4 qv = *reinterpret_cast<const float4*>(&Qg[(size_t)r * DH_ + c]);
        unsigned* p = &Ps[r * PS_STRIDE + c];
        p[0] = f2tf(qv.x); p[1] = f2tf(qv.y); p[2] = f2tf(qv.z); p[3] = f2tf(qv.w);
    }
    __syncthreads();

    // Load Q fragments (8 k-steps over d=64) — warp-local rows of Ps
    unsigned qf[8][4];
    #pragma unroll
    for (int kk = 0; kk < 8; kk++) {
        const int base = (wrp * 16 + g) * PS_STRIDE + kk * 8 + t;
        qf[kk][0] = Ps[base];
        qf[kk][1] = Ps[base + 8 * PS_STRIDE];
        qf[kk][2] = Ps[base + 4];
        qf[kk][3] = Ps[base + 8 * PS_STRIDE + 4];
    }

    float oacc[8][4];
    #pragma unroll
    for (int j = 0; j < 8; j++)
        #pragma unroll
        for (int r = 0; r < 4; r++) oacc[j][r] = 0.0f;
    float m0 = -INFINITY, m1 = -INFINITY, l0 = 0.0f, l1 = 0.0f;

    for (int kt = 0; kt < S_ / 64; kt++) {
        unsigned* Ksb = Ksb_[kt & 1];
        unsigned* Vsb = Vsb_[kt & 1];

        // tile kt arrived + all warps done reading the buffer we'll refill
        cp_wait_all();
        __syncthreads();

        // prefetch tile kt+1 into the other buffer (runs during MMAs below)
        if (kt + 1 < S_ / 64) {
            unsigned* Ksn = Ksb_[(kt + 1) & 1];
            unsigned* Vsn = Vsb_[(kt + 1) & 1];
            const size_t roff = (size_t)(kt + 1) * 64;
            #pragma unroll
            for (int it = 0; it < 4; it++) {
                cp_async16(smem_u32(&Ksn[kv_r[it] * KS_STRIDE + kv_c[it]]),
                           &Kg[(roff + kv_r[it]) * DH_ + kv_c[it]]);
                cp_async16(smem_u32(&Vsn[kv_r[it] * VS_STRIDE + kv_c[it]]),
                           &Vg[(roff + kv_r[it]) * DH_ + kv_c[it]]);
            }
            cp_commit();
        }

        // S = Q @ K^T (warp: m16 x n64, k=64)
        float sacc[8][4];
        #pragma unroll
        for (int j = 0; j < 8; j++)
            #pragma unroll
            for (int r = 0; r < 4; r++) sacc[j][r] = 0.0f;

        #pragma unroll
        for (int kk = 0; kk < 8; kk++) {
            #pragma unroll
            for (int j = 0; j < 8; j++) {
                const int bbase = (j * 8 + g) * KS_STRIDE + kk * 8 + t;
                mma_tf32(sacc[j], qf[kk][0], qf[kk][1], qf[kk][2], qf[kk][3],
                         Ksb[bbase], Ksb[bbase + 4]);
            }
        }

        // scale + online softmax (rows g and g+8 of this warp's m16)
        const float scale = 0.125f;
        float mx0 = -INFINITY, mx1 = -INFINITY;
        #pragma unroll
        for (int j = 0; j < 8; j++) {
            sacc[j][0] *= scale; sacc[j][1] *= scale;
            sacc[j][2] *= scale; sacc[j][3] *= scale;
            mx0 = fmaxf(mx0, fmaxf(sacc[j][0], sacc[j][1]));
            mx1 = fmaxf(mx1, fmaxf(sacc[j][2], sacc[j][3]));
        }
        #pragma unroll
        for (int off = 1; off <= 2; off <<= 1) {
            mx0 = fmaxf(mx0, __shfl_xor_sync(0xffffffffu, mx0, off));
            mx1 = fmaxf(mx1, __shfl_xor_sync(0xffffffffu, mx1, off));
        }
        const float mn0 = fmaxf(m0, mx0);
        const float mn1 = fmaxf(m1, mx1);
        const float corr0 = __expf(m0 - mn0);
        const float corr1 = __expf(m1 - mn1);
        m0 = mn0; m1 = mn1;

        float sum0 = 0.0f, sum1 = 0.0f;
        #pragma unroll
        for (int j = 0; j < 8; j++) {
            sacc[j][0] = __expf(sacc[j][0] - mn0);
            sacc[j][1] = __expf(sacc[j][1] - mn0);
            sacc[j][2] = __expf(sacc[j][2] - mn1);
            sacc[j][3] = __expf(sacc[j][3] - mn1);
            sum0 += sacc[j][0] + sacc[j][1];
            sum1 += sacc[j][2] + sacc[j][3];
        }
        #pragma unroll
        for (int off = 1; off <= 2; off <<= 1) {
            sum0 += __shfl_xor_sync(0xffffffffu, sum0, off);
            sum1 += __shfl_xor_sync(0xffffffffu, sum1, off);
        }
        l0 = l0 * corr0 + sum0;
        l1 = l1 * corr1 + sum1;

        #pragma unroll
        for (int j = 0; j < 8; j++) {
            oacc[j][0] *= corr0; oacc[j][1] *= corr0;
            oacc[j][2] *= corr1; oacc[j][3] *= corr1;
        }

        // store P (tf32) into Ps — warp-local rows only
        #pragma unroll
        for (int j = 0; j < 8; j++) {
            const int base = (wrp * 16 + g) * PS_STRIDE + j * 8 + 2 * t;
            Ps[base]     = f2tf(sacc[j][0]);
            Ps[base + 1] = f2tf(sacc[j][1]);
            Ps[base + 8 * PS_STRIDE]     = f2tf(sacc[j][2]);
            Ps[base + 8 * PS_STRIDE + 1] = f2tf(sacc[j][3]);
        }
        __syncwarp();

        // O += P @ V
        #pragma unroll
        for (int kk = 0; kk < 8; kk++) {
            const int abase = (wrp * 16 + g) * PS_STRIDE + kk * 8 + t;
            const unsigned a0 = Ps[abase];
            const unsigned a1 = Ps[abase + 8 * PS_STRIDE];
            const unsigned a2 = Ps[abase + 4];
            const unsigned a3 = Ps[abase + 8 * PS_STRIDE + 4];
            #pragma unroll
            for (int j = 0; j < 8; j++) {
                const int vb = (kk * 8 + t) * VS_STRIDE + j * 8 + g;
                mma_tf32(oacc[j], a0, a1, a2, a3, Vsb[vb], Vsb[vb + 4 * VS_STRIDE]);
            }
        }
    }

    // Final: normalize + store [B, S, D]
    const float inv0 = 1.0f / l0;
    const float inv1 = 1.0f / l1;
    const int row0 = qt * 128 + wrp * 16 + g;
    const int row1 = row0 + 8;
    const size_t o0 = ((size_t)(b * S_ + row0)) * D_ + h * DH_;
    const size_t o1 = ((size_t)(b * S_ + row1)) * D_ + h * DH_;
    #pragma unroll
    for (int j = 0; j < 8; j++) {
        const int d = j * 8 + 2 * t;
        *reinterpret_cast<float2*>(&out[o0 + d]) =
            make_float2(oacc[j][0] * inv0, oacc[j][1] * inv0);
        *reinterpret_cast<float2*>(&out[o1 + d]) =
            make_float2(oacc[j][2] * inv1, oacc[j][3] * inv1);
    }
}

// ---------------------------------------------------------------------------
extern "C" void kernel_launch(void* const* d_in, const int* in_sizes, int n_in,
                              void* d_out, int out_size)
{
    const float* x  = (const float*)d_in[0];
    const float* Wq = (const float*)d_in[1];
    const float* bq = (const float*)d_in[2];
    const float* Wk = (const float*)d_in[3];
    const float* bk = (const float*)d_in[4];
    const float* Wv = (const float*)d_in[5];
    const float* bv = (const float*)d_in[6];
    float* out = (float*)d_out;

    dim3 g1(D_ / 128, M_ / 128, 3);
    qkv_gemm_tc<<<g1, 256>>>(x, Wq, bq, Wk, bk, Wv, bv);

    const int smem_bytes = ATTN_SMEM_U32 * sizeof(unsigned);
    cudaFuncSetAttribute(attn_tc,
                         cudaFuncAttributeMaxDynamicSharedMemorySize, smem_bytes);
    dim3 g2(S_ / 128, H_, B_);
    attn_tc<<<g2, 256, smem_bytes>>>(out);
}

// round 7
// speedup vs baseline: 1.3662x; 1.0212x over previous
#include <cuda_runtime.h>
#include <cuda_bf16.h>
#include <math.h>

// Problem constants
#define B_  4
#define S_  2048
#define D_  1024
#define H_  16
#define DH_ 64
#define M_  (B_ * S_)

// Scratch for projected Q, K, V in [B, H, S, Dh] layout (fp32)
__device__ float g_Q[B_ * H_ * S_ * DH_];
__device__ float g_K[B_ * H_ * S_ * DH_];
__device__ float g_V[B_ * H_ * S_ * DH_];

// ---------------------------------------------------------------------------
// Helpers
// ---------------------------------------------------------------------------
__device__ __forceinline__ unsigned f2tf(float f) {
    unsigned u;
    asm("cvt.rna.tf32.f32 %0, %1;" : "=r"(u) : "f"(f));
    return u;
}

__device__ __forceinline__ void mma_tf32(float c[4],
                                         unsigned a0, unsigned a1, unsigned a2, unsigned a3,
                                         unsigned b0, unsigned b1) {
    asm volatile(
        "mma.sync.aligned.m16n8k8.row.col.f32.tf32.tf32.f32 "
        "{%0,%1,%2,%3}, {%4,%5,%6,%7}, {%8,%9}, {%0,%1,%2,%3};"
        : "+f"(c[0]), "+f"(c[1]), "+f"(c[2]), "+f"(c[3])
        : "r"(a0), "r"(a1), "r"(a2), "r"(a3), "r"(b0), "r"(b1));
}

__device__ __forceinline__ unsigned smem_u32(const void* p) {
    unsigned a;
    asm("{ .reg .u64 t; cvta.to.shared.u64 t, %1; cvt.u32.u64 %0, t; }"
        : "=r"(a) : "l"(p));
    return a;
}

__device__ __forceinline__ void cp_async16(unsigned saddr, const void* gptr) {
    asm volatile("cp.async.cg.shared.global [%0], [%1], 16;"
                 :: "r"(saddr), "l"(gptr));
}
__device__ __forceinline__ void cp_commit() {
    asm volatile("cp.async.commit_group;");
}
__device__ __forceinline__ void cp_wait_all() {
    asm volatile("cp.async.wait_group 0;");
}

// ---------------------------------------------------------------------------
// Kernel 1: QKV projection GEMM (tf32 mma) — unchanged from best (R2 shape).
// BM=128, BN=128, BK=16; 8 warps (2x4); warp tile 64x32.
// ---------------------------------------------------------------------------
#define AS_STRIDE 20
#define BS_STRIDE 136

__global__ __launch_bounds__(256)
void qkv_gemm_tc(const float* __restrict__ X,
                 const float* __restrict__ Wq, const float* __restrict__ bq,
                 const float* __restrict__ Wk, const float* __restrict__ bk,
                 const float* __restrict__ Wv, const float* __restrict__ bv)
{
    __shared__ unsigned As[128 * AS_STRIDE];
    __shared__ unsigned Bs[16 * BS_STRIDE];

    const int tid  = threadIdx.x;
    const int lane = tid & 31;
    const int wrp  = tid >> 5;
    const int g    = lane >> 2;
    const int t    = lane & 3;
    const int wm   = wrp >> 2;
    const int wn   = wrp & 3;

    const int m0 = blockIdx.y * 128;
    const int n0 = blockIdx.x * 128;
    const int z  = blockIdx.z;

    const float* W    = (z == 0) ? Wq : (z == 1) ? Wk : Wv;
    const float* bias = (z == 0) ? bq : (z == 1) ? bk : bv;
    float* dst        = (z == 0) ? g_Q : (z == 1) ? g_K : g_V;

    float acc[4][4][4];
    #pragma unroll
    for (int i = 0; i < 4; i++)
        #pragma unroll
        for (int j = 0; j < 4; j++)
            #pragma unroll
            for (int r = 0; r < 4; r++) acc[i][j][r] = 0.0f;

    int a_row[2], a_c[2], b_row[2], b_c[2];
    #pragma unroll
    for (int it = 0; it < 2; it++) {
        const int idx = tid + it * 256;
        a_row[it] = idx >> 2;  a_c[it] = (idx & 3) << 2;
        b_row[it] = idx >> 5;  b_c[it] = (idx & 31) << 2;
    }

    float4 ra[2], rb[2];
    #pragma unroll
    for (int it = 0; it < 2; it++) {
        ra[it] = *reinterpret_cast<const float4*>(
            &X[(size_t)(m0 + a_row[it]) * D_ + a_c[it]]);
        rb[it] = *reinterpret_cast<const float4*>(
            &W[(size_t)b_row[it] * D_ + n0 + b_c[it]]);
    }

    for (int kt = 0; kt < D_ / 16; kt++) {
        #pragma unroll
        for (int it = 0; it < 2; it++) {
            unsigned* ap = &As[a_row[it] * AS_STRIDE + a_c[it]];
            ap[0] = f2tf(ra[it].x); ap[1] = f2tf(ra[it].y);
            ap[2] = f2tf(ra[it].z); ap[3] = f2tf(ra[it].w);
            unsigned* bp = &Bs[b_row[it] * BS_STRIDE + b_c[it]];
            bp[0] = f2tf(rb[it].x); bp[1] = f2tf(rb[it].y);
            bp[2] = f2tf(rb[it].z); bp[3] = f2tf(rb[it].w);
        }
        __syncthreads();

        if (kt + 1 < D_ / 16) {
            const int koff = (kt + 1) * 16;
            #pragma unroll
            for (int it = 0; it < 2; it++) {
                ra[it] = *reinterpret_cast<const float4*>(
                    &X[(size_t)(m0 + a_row[it]) * D_ + koff + a_c[it]]);
                rb[it] = *reinterpret_cast<const float4*>(
                    &W[(size_t)(koff + b_row[it]) * D_ + n0 + b_c[it]]);
            }
        }

        #pragma unroll
        for (int ks = 0; ks < 16; ks += 8) {
            unsigned af[4][4];
            #pragma unroll
            for (int i = 0; i < 4; i++) {
                const int rbase = (wm * 64 + i * 16 + g) * AS_STRIDE + ks + t;
                af[i][0] = As[rbase];
                af[i][1] = As[rbase + 8 * AS_STRIDE];
                af[i][2] = As[rbase + 4];
                af[i][3] = As[rbase + 8 * AS_STRIDE + 4];
            }
            unsigned bf[4][2];
            #pragma unroll
            for (int j = 0; j < 4; j++) {
                const int bbase = (ks + t) * BS_STRIDE + wn * 32 + j * 8 + g;
                bf[j][0] = Bs[bbase];
                bf[j][1] = Bs[bbase + 4 * BS_STRIDE];
            }
            #pragma unroll
            for (int i = 0; i < 4; i++)
                #pragma unroll
                for (int j = 0; j < 4; j++)
                    mma_tf32(acc[i][j], af[i][0], af[i][1], af[i][2], af[i][3],
                             bf[j][0], bf[j][1]);
        }
        __syncthreads();
    }

    #pragma unroll
    for (int i = 0; i < 4; i++) {
        const int mrow0 = m0 + wm * 64 + i * 16 + g;
        const int mrow1 = mrow0 + 8;
        #pragma unroll
        for (int j = 0; j < 4; j++) {
            const int n = n0 + wn * 32 + j * 8 + 2 * t;
            const int h = n >> 6;
            const int d = n & 63;
            const float b0v = bias[n], b1v = bias[n + 1];
            {
                const int bb = mrow0 >> 11, s = mrow0 & 2047;
                float2 v = make_float2(acc[i][j][0] + b0v, acc[i][j][1] + b1v);
                *reinterpret_cast<float2*>(
                    &dst[(((size_t)(bb * H_ + h)) * S_ + s) * DH_ + d]) = v;
            }
            {
                const int bb = mrow1 >> 11, s = mrow1 & 2047;
                float2 v = make_float2(acc[i][j][2] + b0v, acc[i][j][3] + b1v);
                *reinterpret_cast<float2*>(
                    &dst[(((size_t)(bb * H_ + h)) * S_ + s) * DH_ + d]) = v;
            }
        }
    }
}

// ---------------------------------------------------------------------------
// Kernel 2: flash attention (tf32 mma), cp.async double-buffered K/V.
// NOW: 128 threads (4 warps), Q tile 64 rows -> ~87KB smem -> 2 CTAs/SM.
// Two independent CTAs per SM overlap softmax of one with MMAs of the other.
// smem (u32): Ks[2][64*68] | Vs[2][64*72] | Ps[64*68]
// ---------------------------------------------------------------------------
#define KS_STRIDE 68
#define VS_STRIDE 72
#define PS_STRIDE 68
#define QT_ROWS 64
#define ATTN_SMEM_U32 (2 * 64 * KS_STRIDE + 2 * 64 * VS_STRIDE + QT_ROWS * PS_STRIDE)

__global__ __launch_bounds__(128)
void attn_tc(float* __restrict__ out)
{
    extern __shared__ unsigned sm_u[];
    unsigned* Ksb_[2] = { sm_u, sm_u + 64 * KS_STRIDE };
    unsigned* Vsb_[2] = { sm_u + 2 * 64 * KS_STRIDE,
                          sm_u + 2 * 64 * KS_STRIDE + 64 * VS_STRIDE };
    unsigned* Ps = sm_u + 2 * 64 * KS_STRIDE + 2 * 64 * VS_STRIDE;

    const int tid  = threadIdx.x;           // 0..127
    const int lane = tid & 31;
    const int wrp  = tid >> 5;              // 0..3
    const int g    = lane >> 2;
    const int t    = lane & 3;

    const int qt = blockIdx.x;              // 0..31
    const int h  = blockIdx.y;
    const int b  = blockIdx.z;

    const size_t head_base = ((size_t)(b * H_ + h)) * S_ * DH_;
    const float* Qg = g_Q + head_base + (size_t)qt * QT_ROWS * DH_;
    const float* Kg = g_K + head_base;
    const float* Vg = g_V + head_base;

    // per-thread staging coords: 8 float4 of K + 8 of V per tile
    int kv_r[8], kv_c[8];
    #pragma unroll
    for (int it = 0; it < 8; it++) {
        const int idx = tid + it * 128;
        kv_r[it] = idx >> 4;
        kv_c[it] = (idx & 15) << 2;
    }

    // issue tile-0 K/V cp.asyncs (in flight during Q staging)
    #pragma unroll
    for (int it = 0; it < 8; it++) {
        cp_async16(smem_u32(&Ksb_[0][kv_r[it] * KS_STRIDE + kv_c[it]]),
                   &Kg[(size_t)kv_r[it] * DH_ + kv_c[it]]);
        cp_async16(smem_u32(&Vsb_[0][kv_r[it] * VS_STRIDE + kv_c[it]]),
                   &Vg[(size_t)kv_r[it] * DH_ + kv_c[it]]);
    }
    cp_commit();

    // Stage Q (64x64) into Ps, cvt tf32
    #pragma unroll
    for (int it = 0; it < 8; it++) {
        const int idx = tid + it * 128;     // 0..1023 float4s
        const int r = idx >> 4;
        const int c = (idx & 15) << 2;
        float4 qv = *reinterpret_cast<const float4*>(&Qg[(size_t)r * DH_ + c]);
        unsigned* p = &Ps[r * PS_STRIDE + c];
        p[0] = f2tf(qv.x); p[1] = f2tf(qv.y); p[2] = f2tf(qv.z); p[3] = f2tf(qv.w);
    }
    __syncthreads();

    // Load Q fragments (8 k-steps over d=64) — warp-local rows of Ps
    unsigned qf[8][4];
    #pragma unroll
    for (int kk = 0; kk < 8; kk++) {
        const int base = (wrp * 16 + g) * PS_STRIDE + kk * 8 + t;
        qf[kk][0] = Ps[base];
        qf[kk][1] = Ps[base + 8 * PS_STRIDE];
        qf[kk][2] = Ps[base + 4];
        qf[kk][3] = Ps[base + 8 * PS_STRIDE + 4];
    }

    float oacc[8][4];
    #pragma unroll
    for (int j = 0; j < 8; j++)
        #pragma unroll
        for (int r = 0; r < 4; r++) oacc[j][r] = 0.0f;
    float m0 = -INFINITY, m1 = -INFINITY, l0 = 0.0f, l1 = 0.0f;

    for (int kt = 0; kt < S_ / 64; kt++) {
        unsigned* Ksb = Ksb_[kt & 1];
        unsigned* Vsb = Vsb_[kt & 1];

        // tile kt arrived + all warps done reading the buffer we'll refill
        cp_wait_all();
        __syncthreads();

        // prefetch tile kt+1 into the other buffer (runs during MMAs below)
        if (kt + 1 < S_ / 64) {
            unsigned* Ksn = Ksb_[(kt + 1) & 1];
            unsigned* Vsn = Vsb_[(kt + 1) & 1];
            const size_t roff = (size_t)(kt + 1) * 64;
            #pragma unroll
            for (int it = 0; it < 8; it++) {
                cp_async16(smem_u32(&Ksn[kv_r[it] * KS_STRIDE + kv_c[it]]),
                           &Kg[(roff + kv_r[it]) * DH_ + kv_c[it]]);
                cp_async16(smem_u32(&Vsn[kv_r[it] * VS_STRIDE + kv_c[it]]),
                           &Vg[(roff + kv_r[it]) * DH_ + kv_c[it]]);
            }
            cp_commit();
        }

        // S = Q @ K^T (warp: m16 x n64, k=64)
        float sacc[8][4];
        #pragma unroll
        for (int j = 0; j < 8; j++)
            #pragma unroll
            for (int r = 0; r < 4; r++) sacc[j][r] = 0.0f;

        #pragma unroll
        for (int kk = 0; kk < 8; kk++) {
            #pragma unroll
            for (int j = 0; j < 8; j++) {
                const int bbase = (j * 8 + g) * KS_STRIDE + kk * 8 + t;
                mma_tf32(sacc[j], qf[kk][0], qf[kk][1], qf[kk][2], qf[kk][3],
                         Ksb[bbase], Ksb[bbase + 4]);
            }
        }

        // scale + online softmax (rows g and g+8 of this warp's m16)
        const float scale = 0.125f;
        float mx0 = -INFINITY, mx1 = -INFINITY;
        #pragma unroll
        for (int j = 0; j < 8; j++) {
            sacc[j][0] *= scale; sacc[j][1] *= scale;
            sacc[j][2] *= scale; sacc[j][3] *= scale;
            mx0 = fmaxf(mx0, fmaxf(sacc[j][0], sacc[j][1]));
            mx1 = fmaxf(mx1, fmaxf(sacc[j][2], sacc[j][3]));
        }
        #pragma unroll
        for (int off = 1; off <= 2; off <<= 1) {
            mx0 = fmaxf(mx0, __shfl_xor_sync(0xffffffffu, mx0, off));
            mx1 = fmaxf(mx1, __shfl_xor_sync(0xffffffffu, mx1, off));
        }
        const float mn0 = fmaxf(m0, mx0);
        const float mn1 = fmaxf(m1, mx1);
        const float corr0 = __expf(m0 - mn0);
        const float corr1 = __expf(m1 - mn1);
        m0 = mn0; m1 = mn1;

        float sum0 = 0.0f, sum1 = 0.0f;
        #pragma unroll
        for (int j = 0; j < 8; j++) {
            sacc[j][0] = __expf(sacc[j][0] - mn0);
            sacc[j][1] = __expf(sacc[j][1] - mn0);
            sacc[j][2] = __expf(sacc[j][2] - mn1);
            sacc[j][3] = __expf(sacc[j][3] - mn1);
            sum0 += sacc[j][0] + sacc[j][1];
            sum1 += sacc[j][2] + sacc[j][3];
        }
        #pragma unroll
        for (int off = 1; off <= 2; off <<= 1) {
            sum0 += __shfl_xor_sync(0xffffffffu, sum0, off);
            sum1 += __shfl_xor_sync(0xffffffffu, sum1, off);
        }
        l0 = l0 * corr0 + sum0;
        l1 = l1 * corr1 + sum1;

        #pragma unroll
        for (int j = 0; j < 8; j++) {
            oacc[j][0] *= corr0; oacc[j][1] *= corr0;
            oacc[j][2] *= corr1; oacc[j][3] *= corr1;
        }

        // store P (tf32) into Ps — warp-local rows only
        #pragma unroll
        for (int j = 0; j < 8; j++) {
            const int base = (wrp * 16 + g) * PS_STRIDE + j * 8 + 2 * t;
            Ps[base]     = f2tf(sacc[j][0]);
            Ps[base + 1] = f2tf(sacc[j][1]);
            Ps[base + 8 * PS_STRIDE]     = f2tf(sacc[j][2]);
            Ps[base + 8 * PS_STRIDE + 1] = f2tf(sacc[j][3]);
        }
        __syncwarp();

        // O += P @ V
        #pragma unroll
        for (int kk = 0; kk < 8; kk++) {
            const int abase = (wrp * 16 + g) * PS_STRIDE + kk * 8 + t;
            const unsigned a0 = Ps[abase];
            const unsigned a1 = Ps[abase + 8 * PS_STRIDE];
            const unsigned a2 = Ps[abase + 4];
            const unsigned a3 = Ps[abase + 8 * PS_STRIDE + 4];
            #pragma unroll
            for (int j = 0; j < 8; j++) {
                const int vb = (kk * 8 + t) * VS_STRIDE + j * 8 + g;
                mma_tf32(oacc[j], a0, a1, a2, a3, Vsb[vb], Vsb[vb + 4 * VS_STRIDE]);
            }
        }
    }

    // Final: normalize + store [B, S, D]
    const float inv0 = 1.0f / l0;
    const float inv1 = 1.0f / l1;
    const int row0 = qt * QT_ROWS + wrp * 16 + g;
    const int row1 = row0 + 8;
    const size_t o0 = ((size_t)(b * S_ + row0)) * D_ + h * DH_;
    const size_t o1 = ((size_t)(b * S_ + row1)) * D_ + h * DH_;
    #pragma unroll
    for (int j = 0; j < 8; j++) {
        const int d = j * 8 + 2 * t;
        *reinterpret_cast<float2*>(&out[o0 + d]) =
            make_float2(oacc[j][0] * inv0, oacc[j][1] * inv0);
        *reinterpret_cast<float2*>(&out[o1 + d]) =
            make_float2(oacc[j][2] * inv1, oacc[j][3] * inv1);
    }
}

// ---------------------------------------------------------------------------
extern "C" void kernel_launch(void* const* d_in, const int* in_sizes, int n_in,
                              void* d_out, int out_size)
{
    const float* x  = (const float*)d_in[0];
    const float* Wq = (const float*)d_in[1];
    const float* bq = (const float*)d_in[2];
    const float* Wk = (const float*)d_in[3];
    const float* bk = (const float*)d_in[4];
    const float* Wv = (const float*)d_in[5];
    const float* bv = (const float*)d_in[6];
    float* out = (float*)d_out;

    dim3 g1(D_ / 128, M_ / 128, 3);
    qkv_gemm_tc<<<g1, 256>>>(x, Wq, bq, Wk, bk, Wv, bv);

    const int smem_bytes = ATTN_SMEM_U32 * sizeof(unsigned);
    cudaFuncSetAttribute(attn_tc,
                         cudaFuncAttributeMaxDynamicSharedMemorySize, smem_bytes);
    dim3 g2(S_ / QT_ROWS, H_, B_);
    attn_tc<<<g2, 128, smem_bytes>>>(out);
}

// round 9
// speedup vs baseline: 2.2129x; 1.6198x over previous
#include <cuda_runtime.h>
#include <cuda_fp16.h>
#include <cuda_bf16.h>
#include <math.h>

// Problem constants
#define B_  4
#define S_  2048
#define D_  1024
#define H_  16
#define DH_ 64
#define M_  (B_ * S_)

// Scratch for projected Q, K, V in [B, H, S, Dh] layout (fp16)
__device__ __half g_Q[B_ * H_ * S_ * DH_];
__device__ __half g_K[B_ * H_ * S_ * DH_];
__device__ __half g_V[B_ * H_ * S_ * DH_];

// ---------------------------------------------------------------------------
// Helpers
// ---------------------------------------------------------------------------
__device__ __forceinline__ unsigned f2tf(float f) {
    unsigned u;
    asm("cvt.rna.tf32.f32 %0, %1;" : "=r"(u) : "f"(f));
    return u;
}

__device__ __forceinline__ void mma_tf32(float c[4],
                                         unsigned a0, unsigned a1, unsigned a2, unsigned a3,
                                         unsigned b0, unsigned b1) {
    asm volatile(
        "mma.sync.aligned.m16n8k8.row.col.f32.tf32.tf32.f32 "
        "{%0,%1,%2,%3}, {%4,%5,%6,%7}, {%8,%9}, {%0,%1,%2,%3};"
        : "+f"(c[0]), "+f"(c[1]), "+f"(c[2]), "+f"(c[3])
        : "r"(a0), "r"(a1), "r"(a2), "r"(a3), "r"(b0), "r"(b1));
}

__device__ __forceinline__ void mma_f16(float c[4],
                                        unsigned a0, unsigned a1, unsigned a2, unsigned a3,
                                        unsigned b0, unsigned b1) {
    asm volatile(
        "mma.sync.aligned.m16n8k16.row.col.f32.f16.f16.f32 "
        "{%0,%1,%2,%3}, {%4,%5,%6,%7}, {%8,%9}, {%0,%1,%2,%3};"
        : "+f"(c[0]), "+f"(c[1]), "+f"(c[2]), "+f"(c[3])
        : "r"(a0), "r"(a1), "r"(a2), "r"(a3), "r"(b0), "r"(b1));
}

__device__ __forceinline__ void ldsm_x4_t(unsigned& r0, unsigned& r1,
                                          unsigned& r2, unsigned& r3, unsigned addr) {
    asm volatile(
        "ldmatrix.sync.aligned.m8n8.x4.trans.shared.b16 {%0,%1,%2,%3}, [%4];"
        : "=r"(r0), "=r"(r1), "=r"(r2), "=r"(r3) : "r"(addr));
}

__device__ __forceinline__ unsigned smem_u32(const void* p) {
    unsigned a;
    asm("{ .reg .u64 t; cvta.to.shared.u64 t, %1; cvt.u32.u64 %0, t; }"
        : "=r"(a) : "l"(p));
    return a;
}

__device__ __forceinline__ void cp_async16(unsigned saddr, const void* gptr) {
    asm volatile("cp.async.cg.shared.global [%0], [%1], 16;"
                 :: "r"(saddr), "l"(gptr));
}
__device__ __forceinline__ void cp_commit() {
    asm volatile("cp.async.commit_group;");
}
__device__ __forceinline__ void cp_wait_all() {
    asm volatile("cp.async.wait_group 0;");
}

__device__ __forceinline__ unsigned h2u(float x, float y) {
    __half2 h = __floats2half2_rn(x, y);
    return *reinterpret_cast<unsigned*>(&h);
}

// ---------------------------------------------------------------------------
// Kernel 1: QKV projection GEMM (tf32 mma) — R2 shape; epilogue stores fp16.
// BM=128, BN=128, BK=16; 8 warps (2x4); warp tile 64x32.
// ---------------------------------------------------------------------------
#define AS_STRIDE 20
#define BS_STRIDE 136

__global__ __launch_bounds__(256)
void qkv_gemm_tc(const float* __restrict__ X,
                 const float* __restrict__ Wq, const float* __restrict__ bq,
                 const float* __restrict__ Wk, const float* __restrict__ bk,
                 const float* __restrict__ Wv, const float* __restrict__ bv)
{
    __shared__ unsigned As[128 * AS_STRIDE];
    __shared__ unsigned Bs[16 * BS_STRIDE];

    const int tid  = threadIdx.x;
    const int lane = tid & 31;
    const int wrp  = tid >> 5;
    const int g    = lane >> 2;
    const int t    = lane & 3;
    const int wm   = wrp >> 2;
    const int wn   = wrp & 3;

    const int m0 = blockIdx.y * 128;
    const int n0 = blockIdx.x * 128;
    const int z  = blockIdx.z;

    const float* W    = (z == 0) ? Wq : (z == 1) ? Wk : Wv;
    const float* bias = (z == 0) ? bq : (z == 1) ? bk : bv;
    __half* dst       = (z == 0) ? g_Q : (z == 1) ? g_K : g_V;

    float acc[4][4][4];
    #pragma unroll
    for (int i = 0; i < 4; i++)
        #pragma unroll
        for (int j = 0; j < 4; j++)
            #pragma unroll
            for (int r = 0; r < 4; r++) acc[i][j][r] = 0.0f;

    int a_row[2], a_c[2], b_row[2], b_c[2];
    #pragma unroll
    for (int it = 0; it < 2; it++) {
        const int idx = tid + it * 256;
        a_row[it] = idx >> 2;  a_c[it] = (idx & 3) << 2;
        b_row[it] = idx >> 5;  b_c[it] = (idx & 31) << 2;
    }

    float4 ra[2], rb[2];
    #pragma unroll
    for (int it = 0; it < 2; it++) {
        ra[it] = *reinterpret_cast<const float4*>(
            &X[(size_t)(m0 + a_row[it]) * D_ + a_c[it]]);
        rb[it] = *reinterpret_cast<const float4*>(
            &W[(size_t)b_row[it] * D_ + n0 + b_c[it]]);
    }

    for (int kt = 0; kt < D_ / 16; kt++) {
        #pragma unroll
        for (int it = 0; it < 2; it++) {
            unsigned* ap = &As[a_row[it] * AS_STRIDE + a_c[it]];
            ap[0] = f2tf(ra[it].x); ap[1] = f2tf(ra[it].y);
            ap[2] = f2tf(ra[it].z); ap[3] = f2tf(ra[it].w);
            unsigned* bp = &Bs[b_row[it] * BS_STRIDE + b_c[it]];
            bp[0] = f2tf(rb[it].x); bp[1] = f2tf(rb[it].y);
            bp[2] = f2tf(rb[it].z); bp[3] = f2tf(rb[it].w);
        }
        __syncthreads();

        if (kt + 1 < D_ / 16) {
            const int koff = (kt + 1) * 16;
            #pragma unroll
            for (int it = 0; it < 2; it++) {
                ra[it] = *reinterpret_cast<const float4*>(
                    &X[(size_t)(m0 + a_row[it]) * D_ + koff + a_c[it]]);
                rb[it] = *reinterpret_cast<const float4*>(
                    &W[(size_t)(koff + b_row[it]) * D_ + n0 + b_c[it]]);
            }
        }

        #pragma unroll
        for (int ks = 0; ks < 16; ks += 8) {
            unsigned af[4][4];
            #pragma unroll
            for (int i = 0; i < 4; i++) {
                const int rbase = (wm * 64 + i * 16 + g) * AS_STRIDE + ks + t;
                af[i][0] = As[rbase];
                af[i][1] = As[rbase + 8 * AS_STRIDE];
                af[i][2] = As[rbase + 4];
                af[i][3] = As[rbase + 8 * AS_STRIDE + 4];
            }
            unsigned bf[4][2];
            #pragma unroll
            for (int j = 0; j < 4; j++) {
                const int bbase = (ks + t) * BS_STRIDE + wn * 32 + j * 8 + g;
                bf[j][0] = Bs[bbase];
                bf[j][1] = Bs[bbase + 4 * BS_STRIDE];
            }
            #pragma unroll
            for (int i = 0; i < 4; i++)
                #pragma unroll
                for (int j = 0; j < 4; j++)
                    mma_tf32(acc[i][j], af[i][0], af[i][1], af[i][2], af[i][3],
                             bf[j][0], bf[j][1]);
        }
        __syncthreads();
    }

    // Epilogue: bias + fp16 convert + head-split scatter
    #pragma unroll
    for (int i = 0; i < 4; i++) {
        const int mrow0 = m0 + wm * 64 + i * 16 + g;
        const int mrow1 = mrow0 + 8;
        #pragma unroll
        for (int j = 0; j < 4; j++) {
            const int n = n0 + wn * 32 + j * 8 + 2 * t;
            const int h = n >> 6;
            const int d = n & 63;
            const float b0v = bias[n], b1v = bias[n + 1];
            {
                const int bb = mrow0 >> 11, s = mrow0 & 2047;
                __half2 v = __floats2half2_rn(acc[i][j][0] + b0v, acc[i][j][1] + b1v);
                *reinterpret_cast<__half2*>(
                    &dst[(((size_t)(bb * H_ + h)) * S_ + s) * DH_ + d]) = v;
            }
            {
                const int bb = mrow1 >> 11, s = mrow1 & 2047;
                __half2 v = __floats2half2_rn(acc[i][j][2] + b0v, acc[i][j][3] + b1v);
                *reinterpret_cast<__half2*>(
                    &dst[(((size_t)(bb * H_ + h)) * S_ + s) * DH_ + d]) = v;
            }
        }
    }
}

// ---------------------------------------------------------------------------
// Kernel 2: flash attention, fp16 m16n8k16 mma, fp32 accumulate.
// 128 threads (4 warps), Q tile 64 rows, K/V tiles 64 rows, cp.async
// double-buffered. Q frags via LDG; K b-frags via contiguous LDS.32;
// V b-frags via ldmatrix.x4.trans; P stays in registers (S-layout == A-layout).
// smem: Ks[2][64*72] + Vs[2][64*72] halves = 36KB (static).
// ---------------------------------------------------------------------------
#define KS_STRIDE 72
#define VS_STRIDE 72
#define QT_ROWS 64

__global__ __launch_bounds__(128)
void attn_f16(float* __restrict__ out)
{
    __shared__ __half Ks[2][64 * KS_STRIDE];
    __shared__ __half Vs[2][64 * VS_STRIDE];

    const int tid  = threadIdx.x;
    const int lane = tid & 31;
    const int wrp  = tid >> 5;
    const int g    = lane >> 2;
    const int t    = lane & 3;

    const int qt = blockIdx.x;
    const int h  = blockIdx.y;
    const int b  = blockIdx.z;

    const size_t head_base = ((size_t)(b * H_ + h)) * S_ * DH_;
    const __half* Qg = g_Q + head_base + (size_t)qt * QT_ROWS * DH_;
    const __half* Kg = g_K + head_base;
    const __half* Vg = g_V + head_base;

    // staging coords: 64 rows x 128B; 512 chunks of 16B; 4 per thread per tensor
    int cr[4], cc[4];
    #pragma unroll
    for (int it = 0; it < 4; it++) {
        const int idx = tid + it * 128;
        cr[it] = idx >> 3;              // row 0..63
        cc[it] = (idx & 7) << 3;        // col halves 0..56
    }

    // issue tile-0 K/V cp.asyncs
    #pragma unroll
    for (int it = 0; it < 4; it++) {
        cp_async16(smem_u32(&Ks[0][cr[it] * KS_STRIDE + cc[it]]),
                   &Kg[(size_t)cr[it] * DH_ + cc[it]]);
        cp_async16(smem_u32(&Vs[0][cr[it] * VS_STRIDE + cc[it]]),
                   &Vg[(size_t)cr[it] * DH_ + cc[it]]);
    }
    cp_commit();

    // Q fragments straight from gmem (fp16): rows wrp*16+g, +8; 4 k-steps of 16
    unsigned qf[4][4];
    {
        const int r0 = wrp * 16 + g;
        #pragma unroll
        for (int kk = 0; kk < 4; kk++) {
            const int c = kk * 16 + 2 * t;
            qf[kk][0] = *reinterpret_cast<const unsigned*>(&Qg[(size_t)r0 * DH_ + c]);
            qf[kk][1] = *reinterpret_cast<const unsigned*>(&Qg[(size_t)(r0 + 8) * DH_ + c]);
            qf[kk][2] = *reinterpret_cast<const unsigned*>(&Qg[(size_t)r0 * DH_ + c + 8]);
            qf[kk][3] = *reinterpret_cast<const unsigned*>(&Qg[(size_t)(r0 + 8) * DH_ + c + 8]);
        }
    }

    // ldmatrix.trans lane addressing for V (row within 16, col group)
    const int v_row = (lane & 7) + ((lane >> 3) & 1) * 8;
    const int v_col = (lane >> 4) * 8;

    float oacc[8][4];
    #pragma unroll
    for (int j = 0; j < 8; j++)
        #pragma unroll
        for (int r = 0; r < 4; r++) oacc[j][r] = 0.0f;
    float m0 = -INFINITY, m1 = -INFINITY, l0 = 0.0f, l1 = 0.0f;

    for (int kt = 0; kt < S_ / 64; kt++) {
        const int buf = kt & 1;

        cp_wait_all();
        __syncthreads();

        // prefetch tile kt+1 (in flight during MMAs below)
        if (kt + 1 < S_ / 64) {
            const int nb = (kt + 1) & 1;
            const size_t roff = (size_t)(kt + 1) * 64;
            #pragma unroll
            for (int it = 0; it < 4; it++) {
                cp_async16(smem_u32(&Ks[nb][cr[it] * KS_STRIDE + cc[it]]),
                           &Kg[(roff + cr[it]) * DH_ + cc[it]]);
                cp_async16(smem_u32(&Vs[nb][cr[it] * VS_STRIDE + cc[it]]),
                           &Vg[(roff + cr[it]) * DH_ + cc[it]]);
            }
            cp_commit();
        }

        // S = Q @ K^T : 8 n-tiles x 4 k-steps, b-frags are contiguous half pairs
        float sacc[8][4];
        #pragma unroll
        for (int j = 0; j < 8; j++)
            #pragma unroll
            for (int r = 0; r < 4; r++) sacc[j][r] = 0.0f;

        #pragma unroll
        for (int j = 0; j < 8; j++) {
            const __half* krow = &Ks[buf][(j * 8 + g) * KS_STRIDE + 2 * t];
            #pragma unroll
            for (int kk = 0; kk < 4; kk++) {
                const unsigned b0 = *reinterpret_cast<const unsigned*>(&krow[kk * 16]);
                const unsigned b1 = *reinterpret_cast<const unsigned*>(&krow[kk * 16 + 8]);
                mma_f16(sacc[j], qf[kk][0], qf[kk][1], qf[kk][2], qf[kk][3], b0, b1);
            }
        }

        // scale + online softmax (rows g and g+8)
        const float scale = 0.125f;
        float mx0 = -INFINITY, mx1 = -INFINITY;
        #pragma unroll
        for (int j = 0; j < 8; j++) {
            sacc[j][0] *= scale; sacc[j][1] *= scale;
            sacc[j][2] *= scale; sacc[j][3] *= scale;
            mx0 = fmaxf(mx0, fmaxf(sacc[j][0], sacc[j][1]));
            mx1 = fmaxf(mx1, fmaxf(sacc[j][2], sacc[j][3]));
        }
        #pragma unroll
        for (int off = 1; off <= 2; off <<= 1) {
            mx0 = fmaxf(mx0, __shfl_xor_sync(0xffffffffu, mx0, off));
            mx1 = fmaxf(mx1, __shfl_xor_sync(0xffffffffu, mx1, off));
        }
        const float mn0 = fmaxf(m0, mx0);
        const float mn1 = fmaxf(m1, mx1);
        const float corr0 = __expf(m0 - mn0);
        const float corr1 = __expf(m1 - mn1);
        m0 = mn0; m1 = mn1;

        float sum0 = 0.0f, sum1 = 0.0f;
        #pragma unroll
        for (int j = 0; j < 8; j++) {
            sacc[j][0] = __expf(sacc[j][0] - mn0);
            sacc[j][1] = __expf(sacc[j][1] - mn0);
            sacc[j][2] = __expf(sacc[j][2] - mn1);
            sacc[j][3] = __expf(sacc[j][3] - mn1);
            sum0 += sacc[j][0] + sacc[j][1];
            sum1 += sacc[j][2] + sacc[j][3];
        }
        #pragma unroll
        for (int off = 1; off <= 2; off <<= 1) {
            sum0 += __shfl_xor_sync(0xffffffffu, sum0, off);
            sum1 += __shfl_xor_sync(0xffffffffu, sum1, off);
        }
        l0 = l0 * corr0 + sum0;
        l1 = l1 * corr1 + sum1;

        #pragma unroll
        for (int j = 0; j < 8; j++) {
            oacc[j][0] *= corr0; oacc[j][1] *= corr0;
            oacc[j][2] *= corr1; oacc[j][3] *= corr1;
        }

        // O += P @ V : P stays in registers (S-layout == A-frag layout for k16)
        const unsigned vsbase = smem_u32(&Vs[buf][0]);
        #pragma unroll
        for (int kk = 0; kk < 4; kk++) {
            const unsigned a0 = h2u(sacc[2 * kk][0],     sacc[2 * kk][1]);
            const unsigned a1 = h2u(sacc[2 * kk][2],     sacc[2 * kk][3]);
            const unsigned a2 = h2u(sacc[2 * kk + 1][0], sacc[2 * kk + 1][1]);
            const unsigned a3 = h2u(sacc[2 * kk + 1][2], sacc[2 * kk + 1][3]);
            #pragma unroll
            for (int p = 0; p < 4; p++) {
                unsigned r0, r1, r2, r3;
                const unsigned addr = vsbase +
                    (((kk * 16 + v_row) * VS_STRIDE) + p * 16 + v_col) * 2;
                ldsm_x4_t(r0, r1, r2, r3, addr);
                mma_f16(oacc[2 * p],     a0, a1, a2, a3, r0, r1);
                mma_f16(oacc[2 * p + 1], a0, a1, a2, a3, r2, r3);
            }
        }
    }

    // Final: normalize + store [B, S, D] fp32
    const float inv0 = 1.0f / l0;
    const float inv1 = 1.0f / l1;
    const int row0 = qt * QT_ROWS + wrp * 16 + g;
    const int row1 = row0 + 8;
    const size_t o0 = ((size_t)(b * S_ + row0)) * D_ + h * DH_;
    const size_t o1 = ((size_t)(b * S_ + row1)) * D_ + h * DH_;
    #pragma unroll
    for (int j = 0; j < 8; j++) {
        const int d = j * 8 + 2 * t;
        *reinterpret_cast<float2*>(&out[o0 + d]) =
            make_float2(oacc[j][0] * inv0, oacc[j][1] * inv0);
        *reinterpret_cast<float2*>(&out[o1 + d]) =
            make_float2(oacc[j][2] * inv1, oacc[j][3] * inv1);
    }
}

// ---------------------------------------------------------------------------
extern "C" void kernel_launch(void* const* d_in, const int* in_sizes, int n_in,
                              void* d_out, int out_size)
{
    const float* x  = (const float*)d_in[0];
    const float* Wq = (const float*)d_in[1];
    const float* bq = (const float*)d_in[2];
    const float* Wk = (const float*)d_in[3];
    const float* bk = (const float*)d_in[4];
    const float* Wv = (const float*)d_in[5];
    const float* bv = (const float*)d_in[6];
    float* out = (float*)d_out;

    dim3 g1(D_ / 128, M_ / 128, 3);
    qkv_gemm_tc<<<g1, 256>>>(x, Wq, bq, Wk, bk, Wv, bv);

    dim3 g2(S_ / QT_ROWS, H_, B_);
    attn_f16<<<g2, 128>>>(out);
}

// round 11
// speedup vs baseline: 2.8797x; 1.3014x over previous
#include <cuda_runtime.h>
#include <cuda_fp16.h>
#include <cuda_bf16.h>
#include <math.h>

// Problem constants
#define B_  4
#define S_  2048
#define D_  1024
#define H_  16
#define DH_ 64
#define M_  (B_ * S_)

// Scratch (fp16): projections + converted inputs
__device__ __half g_Q[B_ * H_ * S_ * DH_];     // pre-scaled by 0.125
__device__ __half g_K[B_ * H_ * S_ * DH_];
__device__ __half g_V[B_ * H_ * S_ * DH_];
__device__ __half g_Xh[M_ * D_];               // X in fp16
__device__ __half g_WTh[3 * D_ * D_];          // W^T in fp16: [z][n][k]

// ---------------------------------------------------------------------------
// Helpers
// ---------------------------------------------------------------------------
__device__ __forceinline__ void mma_f16(float c[4],
                                        unsigned a0, unsigned a1, unsigned a2, unsigned a3,
                                        unsigned b0, unsigned b1) {
    asm volatile(
        "mma.sync.aligned.m16n8k16.row.col.f32.f16.f16.f32 "
        "{%0,%1,%2,%3}, {%4,%5,%6,%7}, {%8,%9}, {%0,%1,%2,%3};"
        : "+f"(c[0]), "+f"(c[1]), "+f"(c[2]), "+f"(c[3])
        : "r"(a0), "r"(a1), "r"(a2), "r"(a3), "r"(b0), "r"(b1));
}

__device__ __forceinline__ void ldsm_x4(unsigned& r0, unsigned& r1,
                                        unsigned& r2, unsigned& r3, unsigned addr) {
    asm volatile(
        "ldmatrix.sync.aligned.m8n8.x4.shared.b16 {%0,%1,%2,%3}, [%4];"
        : "=r"(r0), "=r"(r1), "=r"(r2), "=r"(r3) : "r"(addr));
}

__device__ __forceinline__ void ldsm_x4_t(unsigned& r0, unsigned& r1,
                                          unsigned& r2, unsigned& r3, unsigned addr) {
    asm volatile(
        "ldmatrix.sync.aligned.m8n8.x4.trans.shared.b16 {%0,%1,%2,%3}, [%4];"
        : "=r"(r0), "=r"(r1), "=r"(r2), "=r"(r3) : "r"(addr));
}

__device__ __forceinline__ unsigned smem_u32(const void* p) {
    unsigned a;
    asm("{ .reg .u64 t; cvta.to.shared.u64 t, %1; cvt.u32.u64 %0, t; }"
        : "=r"(a) : "l"(p));
    return a;
}

__device__ __forceinline__ void cp_async16(unsigned saddr, const void* gptr) {
    asm volatile("cp.async.cg.shared.global [%0], [%1], 16;"
                 :: "r"(saddr), "l"(gptr));
}
__device__ __forceinline__ void cp_commit() {
    asm volatile("cp.async.commit_group;");
}
__device__ __forceinline__ void cp_wait_all() {
    asm volatile("cp.async.wait_group 0;");
}

__device__ __forceinline__ unsigned h2u(float x, float y) {
    __half2 h = __floats2half2_rn(x, y);
    return *reinterpret_cast<unsigned*>(&h);
}

// ---------------------------------------------------------------------------
// Pre-pass A: X (fp32) -> g_Xh (fp16)
// ---------------------------------------------------------------------------
__global__ void cvt_x_kernel(const float* __restrict__ X)
{
    const int n4 = M_ * D_ / 4;
    for (int i = blockIdx.x * blockDim.x + threadIdx.x; i < n4;
         i += gridDim.x * blockDim.x) {
        float4 v = reinterpret_cast<const float4*>(X)[i];
        __half2 h0 = __floats2half2_rn(v.x, v.y);
        __half2 h1 = __floats2half2_rn(v.z, v.w);
        uint2 o;
        o.x = *reinterpret_cast<unsigned*>(&h0);
        o.y = *reinterpret_cast<unsigned*>(&h1);
        reinterpret_cast<uint2*>(g_Xh)[i] = o;
    }
}

// ---------------------------------------------------------------------------
// Pre-pass B: W (fp32 [K][N]) -> g_WTh (fp16 [N][K])
// ---------------------------------------------------------------------------
__global__ void cvt_w_kernel(const float* __restrict__ Wq,
                             const float* __restrict__ Wk,
                             const float* __restrict__ Wv)
{
    __shared__ float tile[32][33];
    const int z = blockIdx.z;
    const float* W = (z == 0) ? Wq : (z == 1) ? Wk : Wv;
    __half* WT = g_WTh + (size_t)z * D_ * D_;
    const int x0 = blockIdx.x * 32, y0 = blockIdx.y * 32;
    for (int dy = threadIdx.y; dy < 32; dy += 8)
        tile[dy][threadIdx.x] = W[(size_t)(y0 + dy) * D_ + x0 + threadIdx.x];
    __syncthreads();
    for (int dy = threadIdx.y; dy < 32; dy += 8)
        WT[(size_t)(x0 + dy) * D_ + y0 + threadIdx.x] = __float2half_rn(tile[threadIdx.x][dy]);
}

// ---------------------------------------------------------------------------
// Kernel 1: QKV projection GEMM, fp16 m16n8k16, fp32 accumulate.
// BM=128, BN=128, BK=64; 256 threads (8 warps, 2x4); warp tile 64x32.
// A = g_Xh [m][k], B = g_WTh [n][k] (both k-contiguous fp16).
// smem (half): As[2][128*72], Bs[2][128*72]  (dynamic, ~74KB)
// ---------------------------------------------------------------------------
#define GS 72                    // smem row stride in halves
#define G_BUF (128 * GS)         // halves per tensor per buffer

__global__ __launch_bounds__(256)
void qkv_gemm_f16(const float* __restrict__ bq,
                  const float* __restrict__ bk,
                  const float* __restrict__ bv)
{
    extern __shared__ __half gsm[];
    __half* As_[2] = { gsm,             gsm + 2 * G_BUF };
    __half* Bs_[2] = { gsm + G_BUF,     gsm + 3 * G_BUF };

    const int tid  = threadIdx.x;
    const int lane = tid & 31;
    const int wrp  = tid >> 5;
    const int g    = lane >> 2;
    const int t    = lane & 3;
    const int wm   = wrp >> 2;        // 0..1 (m offset wm*64)
    const int wn   = wrp & 3;         // 0..3 (n offset wn*32)

    const int n0 = blockIdx.x * 128;
    const int m0 = blockIdx.y * 128;
    const int z  = blockIdx.z;

    const float* bias = (z == 0) ? bq : (z == 1) ? bk : bv;
    __half* dst       = (z == 0) ? g_Q : (z == 1) ? g_K : g_V;
    const float oscale = (z == 0) ? 0.125f : 1.0f;   // fold softmax scale into Q
    const __half* Ah = g_Xh + (size_t)m0 * D_;
    const __half* Bh = g_WTh + (size_t)z * D_ * D_ + (size_t)n0 * D_;

    // staging coords: 128 rows x 64 halves = 1024 16B-chunks per tensor
    int sr[4], sc[4];
    #pragma unroll
    for (int it = 0; it < 4; it++) {
        const int idx = tid + it * 256;
        sr[it] = idx >> 3;              // 0..127
        sc[it] = (idx & 7) << 3;        // halves 0..56
    }

    // prologue: stage k-tile 0
    #pragma unroll
    for (int it = 0; it < 4; it++) {
        cp_async16(smem_u32(&As_[0][sr[it] * GS + sc[it]]),
                   &Ah[(size_t)sr[it] * D_ + sc[it]]);
        cp_async16(smem_u32(&Bs_[0][sr[it] * GS + sc[it]]),
                   &Bh[(size_t)sr[it] * D_ + sc[it]]);
    }
    cp_commit();

    float acc[4][4][4];
    #pragma unroll
    for (int i = 0; i < 4; i++)
        #pragma unroll
        for (int j = 0; j < 4; j++)
            #pragma unroll
            for (int r = 0; r < 4; r++) acc[i][j][r] = 0.0f;

    // ldmatrix lane addressing for A (m16k16 tiles)
    const int a_row = lane & 15;
    const int a_col = (lane >> 4) << 3;

    for (int kt = 0; kt < D_ / 64; kt++) {
        const int buf = kt & 1;
        cp_wait_all();
        __syncthreads();

        // prefetch next k-tile
        if (kt + 1 < D_ / 64) {
            const int nb = (kt + 1) & 1;
            const int k0 = (kt + 1) * 64;
            #pragma unroll
            for (int it = 0; it < 4; it++) {
                cp_async16(smem_u32(&As_[nb][sr[it] * GS + sc[it]]),
                           &Ah[(size_t)sr[it] * D_ + k0 + sc[it]]);
                cp_async16(smem_u32(&Bs_[nb][sr[it] * GS + sc[it]]),
                           &Bh[(size_t)sr[it] * D_ + k0 + sc[it]]);
            }
            cp_commit();
        }

        const unsigned asb = smem_u32(As_[buf]);
        #pragma unroll
        for (int kk = 0; kk < 4; kk++) {
            // A fragments: 4 m-tiles via ldmatrix.x4
            unsigned af[4][4];
            #pragma unroll
            for (int i = 0; i < 4; i++) {
                const unsigned addr = asb +
                    ((wm * 64 + i * 16 + a_row) * GS + kk * 16 + a_col) * 2;
                ldsm_x4(af[i][0], af[i][1], af[i][2], af[i][3], addr);
            }
            // B fragments: contiguous half-pairs from [n][k] rows
            unsigned bf[4][2];
            #pragma unroll
            for (int j = 0; j < 4; j++) {
                const __half* brow = &Bs_[buf][(wn * 32 + j * 8 + g) * GS + kk * 16 + 2 * t];
                bf[j][0] = *reinterpret_cast<const unsigned*>(brow);
                bf[j][1] = *reinterpret_cast<const unsigned*>(brow + 8);
            }
            #pragma unroll
            for (int i = 0; i < 4; i++)
                #pragma unroll
                for (int j = 0; j < 4; j++)
                    mma_f16(acc[i][j], af[i][0], af[i][1], af[i][2], af[i][3],
                            bf[j][0], bf[j][1]);
        }
    }

    // Epilogue: bias (+Q scale) + fp16 convert + head-split scatter
    #pragma unroll
    for (int i = 0; i < 4; i++) {
        const int mrow0 = m0 + wm * 64 + i * 16 + g;
        const int mrow1 = mrow0 + 8;
        #pragma unroll
        for (int j = 0; j < 4; j++) {
            const int n = n0 + wn * 32 + j * 8 + 2 * t;
            const int h = n >> 6;
            const int d = n & 63;
            const float b0v = bias[n], b1v = bias[n + 1];
            {
                const int bb = mrow0 >> 11, s = mrow0 & 2047;
                __half2 v = __floats2half2_rn((acc[i][j][0] + b0v) * oscale,
                                              (acc[i][j][1] + b1v) * oscale);
                *reinterpret_cast<__half2*>(
                    &dst[(((size_t)(bb * H_ + h)) * S_ + s) * DH_ + d]) = v;
            }
            {
                const int bb = mrow1 >> 11, s = mrow1 & 2047;
                __half2 v = __floats2half2_rn((acc[i][j][2] + b0v) * oscale,
                                              (acc[i][j][3] + b1v) * oscale);
                *reinterpret_cast<__half2*>(
                    &dst[(((size_t)(bb * H_ + h)) * S_ + s) * DH_ + d]) = v;
            }
        }
    }
}

// ---------------------------------------------------------------------------
// Kernel 2: flash attention, fp16 m16n8k16 (unchanged from R9 except the
// softmax scale is gone — Q arrives pre-scaled by 0.125).
// ---------------------------------------------------------------------------
#define KS_STRIDE 72
#define VS_STRIDE 72
#define QT_ROWS 64

__global__ __launch_bounds__(128)
void attn_f16(float* __restrict__ out)
{
    __shared__ __half Ks[2][64 * KS_STRIDE];
    __shared__ __half Vs[2][64 * VS_STRIDE];

    const int tid  = threadIdx.x;
    const int lane = tid & 31;
    const int wrp  = tid >> 5;
    const int g    = lane >> 2;
    const int t    = lane & 3;

    const int qt = blockIdx.x;
    const int h  = blockIdx.y;
    const int b  = blockIdx.z;

    const size_t head_base = ((size_t)(b * H_ + h)) * S_ * DH_;
    const __half* Qg = g_Q + head_base + (size_t)qt * QT_ROWS * DH_;
    const __half* Kg = g_K + head_base;
    const __half* Vg = g_V + head_base;

    int cr[4], cc[4];
    #pragma unroll
    for (int it = 0; it < 4; it++) {
        const int idx = tid + it * 128;
        cr[it] = idx >> 3;
        cc[it] = (idx & 7) << 3;
    }

    #pragma unroll
    for (int it = 0; it < 4; it++) {
        cp_async16(smem_u32(&Ks[0][cr[it] * KS_STRIDE + cc[it]]),
                   &Kg[(size_t)cr[it] * DH_ + cc[it]]);
        cp_async16(smem_u32(&Vs[0][cr[it] * VS_STRIDE + cc[it]]),
                   &Vg[(size_t)cr[it] * DH_ + cc[it]]);
    }
    cp_commit();

    // Q fragments straight from gmem (fp16, pre-scaled)
    unsigned qf[4][4];
    {
        const int r0 = wrp * 16 + g;
        #pragma unroll
        for (int kk = 0; kk < 4; kk++) {
            const int c = kk * 16 + 2 * t;
            qf[kk][0] = *reinterpret_cast<const unsigned*>(&Qg[(size_t)r0 * DH_ + c]);
            qf[kk][1] = *reinterpret_cast<const unsigned*>(&Qg[(size_t)(r0 + 8) * DH_ + c]);
            qf[kk][2] = *reinterpret_cast<const unsigned*>(&Qg[(size_t)r0 * DH_ + c + 8]);
            qf[kk][3] = *reinterpret_cast<const unsigned*>(&Qg[(size_t)(r0 + 8) * DH_ + c + 8]);
        }
    }

    const int v_row = (lane & 7) + ((lane >> 3) & 1) * 8;
    const int v_col = (lane >> 4) * 8;

    float oacc[8][4];
    #pragma unroll
    for (int j = 0; j < 8; j++)
        #pragma unroll
        for (int r = 0; r < 4; r++) oacc[j][r] = 0.0f;
    float m0 = -INFINITY, m1 = -INFINITY, l0 = 0.0f, l1 = 0.0f;

    for (int kt = 0; kt < S_ / 64; kt++) {
        const int buf = kt & 1;

        cp_wait_all();
        __syncthreads();

        if (kt + 1 < S_ / 64) {
            const int nb = (kt + 1) & 1;
            const size_t roff = (size_t)(kt + 1) * 64;
            #pragma unroll
            for (int it = 0; it < 4; it++) {
                cp_async16(smem_u32(&Ks[nb][cr[it] * KS_STRIDE + cc[it]]),
                           &Kg[(roff + cr[it]) * DH_ + cc[it]]);
                cp_async16(smem_u32(&Vs[nb][cr[it] * VS_STRIDE + cc[it]]),
                           &Vg[(roff + cr[it]) * DH_ + cc[it]]);
            }
            cp_commit();
        }

        float sacc[8][4];
        #pragma unroll
        for (int j = 0; j < 8; j++)
            #pragma unroll
            for (int r = 0; r < 4; r++) sacc[j][r] = 0.0f;

        #pragma unroll
        for (int j = 0; j < 8; j++) {
            const __half* krow = &Ks[buf][(j * 8 + g) * KS_STRIDE + 2 * t];
            #pragma unroll
            for (int kk = 0; kk < 4; kk++) {
                const unsigned b0 = *reinterpret_cast<const unsigned*>(&krow[kk * 16]);
                const unsigned b1 = *reinterpret_cast<const unsigned*>(&krow[kk * 16 + 8]);
                mma_f16(sacc[j], qf[kk][0], qf[kk][1], qf[kk][2], qf[kk][3], b0, b1);
            }
        }

        // online softmax (Q pre-scaled — no mul here)
        float mx0 = -INFINITY, mx1 = -INFINITY;
        #pragma unroll
        for (int j = 0; j < 8; j++) {
            mx0 = fmaxf(mx0, fmaxf(sacc[j][0], sacc[j][1]));
            mx1 = fmaxf(mx1, fmaxf(sacc[j][2], sacc[j][3]));
        }
        #pragma unroll
        for (int off = 1; off <= 2; off <<= 1) {
            mx0 = fmaxf(mx0, __shfl_xor_sync(0xffffffffu, mx0, off));
            mx1 = fmaxf(mx1, __shfl_xor_sync(0xffffffffu, mx1, off));
        }
        const float mn0 = fmaxf(m0, mx0);
        const float mn1 = fmaxf(m1, mx1);
        const float corr0 = __expf(m0 - mn0);
        const float corr1 = __expf(m1 - mn1);
        m0 = mn0; m1 = mn1;

        float sum0 = 0.0f, sum1 = 0.0f;
        #pragma unroll
        for (int j = 0; j < 8; j++) {
            sacc[j][0] = __expf(sacc[j][0] - mn0);
            sacc[j][1] = __expf(sacc[j][1] - mn0);
            sacc[j][2] = __expf(sacc[j][2] - mn1);
            sacc[j][3] = __expf(sacc[j][3] - mn1);
            sum0 += sacc[j][0] + sacc[j][1];
            sum1 += sacc[j][2] + sacc[j][3];
        }
        #pragma unroll
        for (int off = 1; off <= 2; off <<= 1) {
            sum0 += __shfl_xor_sync(0xffffffffu, sum0, off);
            sum1 += __shfl_xor_sync(0xffffffffu, sum1, off);
        }
        l0 = l0 * corr0 + sum0;
        l1 = l1 * corr1 + sum1;

        #pragma unroll
        for (int j = 0; j < 8; j++) {
            oacc[j][0] *= corr0; oacc[j][1] *= corr0;
            oacc[j][2] *= corr1; oacc[j][3] *= corr1;
        }

        // O += P @ V (P in registers; V via ldmatrix.trans)
        const unsigned vsbase = smem_u32(&Vs[buf][0]);
        #pragma unroll
        for (int kk = 0; kk < 4; kk++) {
            const unsigned a0 = h2u(sacc[2 * kk][0],     sacc[2 * kk][1]);
            const unsigned a1 = h2u(sacc[2 * kk][2],     sacc[2 * kk][3]);
            const unsigned a2 = h2u(sacc[2 * kk + 1][0], sacc[2 * kk + 1][1]);
            const unsigned a3 = h2u(sacc[2 * kk + 1][2], sacc[2 * kk + 1][3]);
            #pragma unroll
            for (int p = 0; p < 4; p++) {
                unsigned r0, r1, r2, r3;
                const unsigned addr = vsbase +
                    (((kk * 16 + v_row) * VS_STRIDE) + p * 16 + v_col) * 2;
                ldsm_x4_t(r0, r1, r2, r3, addr);
                mma_f16(oacc[2 * p],     a0, a1, a2, a3, r0, r1);
                mma_f16(oacc[2 * p + 1], a0, a1, a2, a3, r2, r3);
            }
        }
    }

    const float inv0 = 1.0f / l0;
    const float inv1 = 1.0f / l1;
    const int row0 = qt * QT_ROWS + wrp * 16 + g;
    const int row1 = row0 + 8;
    const size_t o0 = ((size_t)(b * S_ + row0)) * D_ + h * DH_;
    const size_t o1 = ((size_t)(b * S_ + row1)) * D_ + h * DH_;
    #pragma unroll
    for (int j = 0; j < 8; j++) {
        const int d = j * 8 + 2 * t;
        *reinterpret_cast<float2*>(&out[o0 + d]) =
            make_float2(oacc[j][0] * inv0, oacc[j][1] * inv0);
        *reinterpret_cast<float2*>(&out[o1 + d]) =
            make_float2(oacc[j][2] * inv1, oacc[j][3] * inv1);
    }
}

// ---------------------------------------------------------------------------
extern "C" void kernel_launch(void* const* d_in, const int* in_sizes, int n_in,
                              void* d_out, int out_size)
{
    const float* x  = (const float*)d_in[0];
    const float* Wq = (const float*)d_in[1];
    const float* bq = (const float*)d_in[2];
    const float* Wk = (const float*)d_in[3];
    const float* bk = (const float*)d_in[4];
    const float* Wv = (const float*)d_in[5];
    const float* bv = (const float*)d_in[6];
    float* out = (float*)d_out;

    // Pre-passes: fp16 conversions
    cvt_x_kernel<<<1024, 256>>>(x);
    cvt_w_kernel<<<dim3(32, 32, 3), dim3(32, 8)>>>(Wq, Wk, Wv);

    // QKV GEMM (fp16 tensor cores)
    const int gsm_bytes = 4 * G_BUF * sizeof(__half);
    cudaFuncSetAttribute(qkv_gemm_f16,
                         cudaFuncAttributeMaxDynamicSharedMemorySize, gsm_bytes);
    qkv_gemm_f16<<<dim3(D_ / 128, M_ / 128, 3), 256, gsm_bytes>>>(bq, bk, bv);

    // Flash attention
    attn_f16<<<dim3(S_ / QT_ROWS, H_, B_), 128>>>(out);
}

// round 12
// speedup vs baseline: 3.2181x; 1.1175x over previous
#include <cuda_runtime.h>
#include <cuda_fp16.h>
#include <cuda_bf16.h>
#include <math.h>

// Problem constants
#define B_  4
#define S_  2048
#define D_  1024
#define H_  16
#define DH_ 64
#define M_  (B_ * S_)

// Scratch (fp16): projections + converted inputs
__device__ __half g_Q[B_ * H_ * S_ * DH_];     // pre-scaled by 0.125*log2(e)
__device__ __half g_K[B_ * H_ * S_ * DH_];
__device__ __half g_V[B_ * H_ * S_ * DH_];
__device__ __half g_Xh[M_ * D_];               // X in fp16
__device__ __half g_WTh[3 * D_ * D_];          // W^T in fp16: [z][n][k]

// ---------------------------------------------------------------------------
// Helpers
// ---------------------------------------------------------------------------
__device__ __forceinline__ void mma_f16(float c[4],
                                        unsigned a0, unsigned a1, unsigned a2, unsigned a3,
                                        unsigned b0, unsigned b1) {
    asm volatile(
        "mma.sync.aligned.m16n8k16.row.col.f32.f16.f16.f32 "
        "{%0,%1,%2,%3}, {%4,%5,%6,%7}, {%8,%9}, {%0,%1,%2,%3};"
        : "+f"(c[0]), "+f"(c[1]), "+f"(c[2]), "+f"(c[3])
        : "r"(a0), "r"(a1), "r"(a2), "r"(a3), "r"(b0), "r"(b1));
}

__device__ __forceinline__ void ldsm_x4(unsigned& r0, unsigned& r1,
                                        unsigned& r2, unsigned& r3, unsigned addr) {
    asm volatile(
        "ldmatrix.sync.aligned.m8n8.x4.shared.b16 {%0,%1,%2,%3}, [%4];"
        : "=r"(r0), "=r"(r1), "=r"(r2), "=r"(r3) : "r"(addr));
}

__device__ __forceinline__ void ldsm_x4_t(unsigned& r0, unsigned& r1,
                                          unsigned& r2, unsigned& r3, unsigned addr) {
    asm volatile(
        "ldmatrix.sync.aligned.m8n8.x4.trans.shared.b16 {%0,%1,%2,%3}, [%4];"
        : "=r"(r0), "=r"(r1), "=r"(r2), "=r"(r3) : "r"(addr));
}

__device__ __forceinline__ unsigned smem_u32(const void* p) {
    unsigned a;
    asm("{ .reg .u64 t; cvta.to.shared.u64 t, %1; cvt.u32.u64 %0, t; }"
        : "=r"(a) : "l"(p));
    return a;
}

__device__ __forceinline__ void cp_async16(unsigned saddr, const void* gptr) {
    asm volatile("cp.async.cg.shared.global [%0], [%1], 16;"
                 :: "r"(saddr), "l"(gptr));
}
__device__ __forceinline__ void cp_commit() {
    asm volatile("cp.async.commit_group;");
}
__device__ __forceinline__ void cp_wait_all() {
    asm volatile("cp.async.wait_group 0;");
}

__device__ __forceinline__ unsigned ex2_h2(unsigned x) {
    unsigned d;
    asm("ex2.approx.f16x2 %0, %1;" : "=r"(d) : "r"(x));
    return d;
}

__device__ __forceinline__ unsigned pack_h2(float x, float y) {
    __half2 h = __floats2half2_rn(x, y);
    return *reinterpret_cast<unsigned*>(&h);
}

#define ONE_H2 0x3C003C00u   // half2(1.0, 1.0)

// ---------------------------------------------------------------------------
// Pre-pass A: X (fp32) -> g_Xh (fp16)
// ---------------------------------------------------------------------------
__global__ void cvt_x_kernel(const float* __restrict__ X)
{
    const int n4 = M_ * D_ / 4;
    for (int i = blockIdx.x * blockDim.x + threadIdx.x; i < n4;
         i += gridDim.x * blockDim.x) {
        float4 v = reinterpret_cast<const float4*>(X)[i];
        __half2 h0 = __floats2half2_rn(v.x, v.y);
        __half2 h1 = __floats2half2_rn(v.z, v.w);
        uint2 o;
        o.x = *reinterpret_cast<unsigned*>(&h0);
        o.y = *reinterpret_cast<unsigned*>(&h1);
        reinterpret_cast<uint2*>(g_Xh)[i] = o;
    }
}

// ---------------------------------------------------------------------------
// Pre-pass B: W (fp32 [K][N]) -> g_WTh (fp16 [N][K])
// ---------------------------------------------------------------------------
__global__ void cvt_w_kernel(const float* __restrict__ Wq,
                             const float* __restrict__ Wk,
                             const float* __restrict__ Wv)
{
    __shared__ float tile[32][33];
    const int z = blockIdx.z;
    const float* W = (z == 0) ? Wq : (z == 1) ? Wk : Wv;
    __half* WT = g_WTh + (size_t)z * D_ * D_;
    const int x0 = blockIdx.x * 32, y0 = blockIdx.y * 32;
    for (int dy = threadIdx.y; dy < 32; dy += 8)
        tile[dy][threadIdx.x] = W[(size_t)(y0 + dy) * D_ + x0 + threadIdx.x];
    __syncthreads();
    for (int dy = threadIdx.y; dy < 32; dy += 8)
        WT[(size_t)(x0 + dy) * D_ + y0 + threadIdx.x] = __float2half_rn(tile[threadIdx.x][dy]);
}

// ---------------------------------------------------------------------------
// Kernel 1: QKV projection GEMM, fp16 m16n8k16, fp32 accumulate.
// BM=128, BN=128, BK=64; 256 threads (8 warps, 2x4); warp tile 64x32.
// Q epilogue scale = 0.125 * log2(e)  (softmax moves to exp2 domain).
// ---------------------------------------------------------------------------
#define GS 72
#define G_BUF (128 * GS)

__global__ __launch_bounds__(256)
void qkv_gemm_f16(const float* __restrict__ bq,
                  const float* __restrict__ bk,
                  const float* __restrict__ bv)
{
    extern __shared__ __half gsm[];
    __half* As_[2] = { gsm,             gsm + 2 * G_BUF };
    __half* Bs_[2] = { gsm + G_BUF,     gsm + 3 * G_BUF };

    const int tid  = threadIdx.x;
    const int lane = tid & 31;
    const int wrp  = tid >> 5;
    const int g    = lane >> 2;
    const int t    = lane & 3;
    const int wm   = wrp >> 2;
    const int wn   = wrp & 3;

    const int n0 = blockIdx.x * 128;
    const int m0 = blockIdx.y * 128;
    const int z  = blockIdx.z;

    const float* bias = (z == 0) ? bq : (z == 1) ? bk : bv;
    __half* dst       = (z == 0) ? g_Q : (z == 1) ? g_K : g_V;
    const float oscale = (z == 0) ? 0.125f * 1.4426950408889634f : 1.0f;
    const __half* Ah = g_Xh + (size_t)m0 * D_;
    const __half* Bh = g_WTh + (size_t)z * D_ * D_ + (size_t)n0 * D_;

    int sr[4], sc[4];
    #pragma unroll
    for (int it = 0; it < 4; it++) {
        const int idx = tid + it * 256;
        sr[it] = idx >> 3;
        sc[it] = (idx & 7) << 3;
    }

    #pragma unroll
    for (int it = 0; it < 4; it++) {
        cp_async16(smem_u32(&As_[0][sr[it] * GS + sc[it]]),
                   &Ah[(size_t)sr[it] * D_ + sc[it]]);
        cp_async16(smem_u32(&Bs_[0][sr[it] * GS + sc[it]]),
                   &Bh[(size_t)sr[it] * D_ + sc[it]]);
    }
    cp_commit();

    float acc[4][4][4];
    #pragma unroll
    for (int i = 0; i < 4; i++)
        #pragma unroll
        for (int j = 0; j < 4; j++)
            #pragma unroll
            for (int r = 0; r < 4; r++) acc[i][j][r] = 0.0f;

    const int a_row = lane & 15;
    const int a_col = (lane >> 4) << 3;

    for (int kt = 0; kt < D_ / 64; kt++) {
        const int buf = kt & 1;
        cp_wait_all();
        __syncthreads();

        if (kt + 1 < D_ / 64) {
            const int nb = (kt + 1) & 1;
            const int k0 = (kt + 1) * 64;
            #pragma unroll
            for (int it = 0; it < 4; it++) {
                cp_async16(smem_u32(&As_[nb][sr[it] * GS + sc[it]]),
                           &Ah[(size_t)sr[it] * D_ + k0 + sc[it]]);
                cp_async16(smem_u32(&Bs_[nb][sr[it] * GS + sc[it]]),
                           &Bh[(size_t)sr[it] * D_ + k0 + sc[it]]);
            }
            cp_commit();
        }

        const unsigned asb = smem_u32(As_[buf]);
        #pragma unroll
        for (int kk = 0; kk < 4; kk++) {
            unsigned af[4][4];
            #pragma unroll
            for (int i = 0; i < 4; i++) {
                const unsigned addr = asb +
                    ((wm * 64 + i * 16 + a_row) * GS + kk * 16 + a_col) * 2;
                ldsm_x4(af[i][0], af[i][1], af[i][2], af[i][3], addr);
            }
            unsigned bf[4][2];
            #pragma unroll
            for (int j = 0; j < 4; j++) {
                const __half* brow = &Bs_[buf][(wn * 32 + j * 8 + g) * GS + kk * 16 + 2 * t];
                bf[j][0] = *reinterpret_cast<const unsigned*>(brow);
                bf[j][1] = *reinterpret_cast<const unsigned*>(brow + 8);
            }
            #pragma unroll
            for (int i = 0; i < 4; i++)
                #pragma unroll
                for (int j = 0; j < 4; j++)
                    mma_f16(acc[i][j], af[i][0], af[i][1], af[i][2], af[i][3],
                            bf[j][0], bf[j][1]);
        }
    }

    #pragma unroll
    for (int i = 0; i < 4; i++) {
        const int mrow0 = m0 + wm * 64 + i * 16 + g;
        const int mrow1 = mrow0 + 8;
        #pragma unroll
        for (int j = 0; j < 4; j++) {
            const int n = n0 + wn * 32 + j * 8 + 2 * t;
            const int h = n >> 6;
            const int d = n & 63;
            const float b0v = bias[n], b1v = bias[n + 1];
            {
                const int bb = mrow0 >> 11, s = mrow0 & 2047;
                __half2 v = __floats2half2_rn((acc[i][j][0] + b0v) * oscale,
                                              (acc[i][j][1] + b1v) * oscale);
                *reinterpret_cast<__half2*>(
                    &dst[(((size_t)(bb * H_ + h)) * S_ + s) * DH_ + d]) = v;
            }
            {
                const int bb = mrow1 >> 11, s = mrow1 & 2047;
                __half2 v = __floats2half2_rn((acc[i][j][2] + b0v) * oscale,
                                              (acc[i][j][3] + b1v) * oscale);
                *reinterpret_cast<__half2*>(
                    &dst[(((size_t)(bb * H_ + h)) * S_ + s) * DH_ + d]) = v;
            }
        }
    }
}

// ---------------------------------------------------------------------------
// Kernel 2: flash attention, fp16 m16n8k16, exp2-domain softmax.
// - K fragments via ldmatrix.x4 (16 LDSM/tile, was 64 LDS.32)
// - P via ex2.approx.f16x2 on packed (s-mn) (results ARE the PV A-frags)
// - row sums l via ones-column MMA accumulator (no sum shuffles)
// ---------------------------------------------------------------------------
#define KS_STRIDE 72
#define VS_STRIDE 72
#define QT_ROWS 64

__global__ __launch_bounds__(128)
void attn_f16(float* __restrict__ out)
{
    __shared__ __half Ks[2][64 * KS_STRIDE];
    __shared__ __half Vs[2][64 * VS_STRIDE];

    const int tid  = threadIdx.x;
    const int lane = tid & 31;
    const int wrp  = tid >> 5;
    const int g    = lane >> 2;
    const int t    = lane & 3;

    const int qt = blockIdx.x;
    const int h  = blockIdx.y;
    const int b  = blockIdx.z;

    const size_t head_base = ((size_t)(b * H_ + h)) * S_ * DH_;
    const __half* Qg = g_Q + head_base + (size_t)qt * QT_ROWS * DH_;
    const __half* Kg = g_K + head_base;
    const __half* Vg = g_V + head_base;

    int cr[4], cc[4];
    #pragma unroll
    for (int it = 0; it < 4; it++) {
        const int idx = tid + it * 128;
        cr[it] = idx >> 3;
        cc[it] = (idx & 7) << 3;
    }

    #pragma unroll
    for (int it = 0; it < 4; it++) {
        cp_async16(smem_u32(&Ks[0][cr[it] * KS_STRIDE + cc[it]]),
                   &Kg[(size_t)cr[it] * DH_ + cc[it]]);
        cp_async16(smem_u32(&Vs[0][cr[it] * VS_STRIDE + cc[it]]),
                   &Vg[(size_t)cr[it] * DH_ + cc[it]]);
    }
    cp_commit();

    // Q fragments from gmem (pre-scaled by 0.125*log2e)
    unsigned qf[4][4];
    {
        const int r0 = wrp * 16 + g;
        #pragma unroll
        for (int kk = 0; kk < 4; kk++) {
            const int c = kk * 16 + 2 * t;
            qf[kk][0] = *reinterpret_cast<const unsigned*>(&Qg[(size_t)r0 * DH_ + c]);
            qf[kk][1] = *reinterpret_cast<const unsigned*>(&Qg[(size_t)(r0 + 8) * DH_ + c]);
            qf[kk][2] = *reinterpret_cast<const unsigned*>(&Qg[(size_t)r0 * DH_ + c + 8]);
            qf[kk][3] = *reinterpret_cast<const unsigned*>(&Qg[(size_t)(r0 + 8) * DH_ + c + 8]);
        }
    }

    // ldmatrix lane addressing
    const int v_row = (lane & 7) + ((lane >> 3) & 1) * 8;          // V (trans)
    const int v_col = (lane >> 4) * 8;
    const int k_nrow = ((lane >> 4) << 3) + (lane & 7);            // K (non-trans)
    const int k_koff = ((lane >> 3) & 1) * 8;

    float oacc[8][4];
    #pragma unroll
    for (int j = 0; j < 8; j++)
        #pragma unroll
        for (int r = 0; r < 4; r++) oacc[j][r] = 0.0f;
    float ol[4] = {0.0f, 0.0f, 0.0f, 0.0f};   // row-sum accumulator (ones MMA)
    float m0 = -INFINITY, m1 = -INFINITY;

    for (int kt = 0; kt < S_ / 64; kt++) {
        const int buf = kt & 1;

        cp_wait_all();
        __syncthreads();

        if (kt + 1 < S_ / 64) {
            const int nb = (kt + 1) & 1;
            const size_t roff = (size_t)(kt + 1) * 64;
            #pragma unroll
            for (int it = 0; it < 4; it++) {
                cp_async16(smem_u32(&Ks[nb][cr[it] * KS_STRIDE + cc[it]]),
                           &Kg[(roff + cr[it]) * DH_ + cc[it]]);
                cp_async16(smem_u32(&Vs[nb][cr[it] * VS_STRIDE + cc[it]]),
                           &Vg[(roff + cr[it]) * DH_ + cc[it]]);
            }
            cp_commit();
        }

        // S = Q @ K^T (log2 domain); K frags via ldmatrix.x4
        float sacc[8][4];
        #pragma unroll
        for (int j = 0; j < 8; j++)
            #pragma unroll
            for (int r = 0; r < 4; r++) sacc[j][r] = 0.0f;

        const unsigned ksb = smem_u32(&Ks[buf][0]);
        #pragma unroll
        for (int jp = 0; jp < 4; jp++) {
            #pragma unroll
            for (int kk = 0; kk < 4; kk++) {
                unsigned b0a, b1a, b0b, b1b;
                const unsigned addr = ksb +
                    (((jp * 16 + k_nrow) * KS_STRIDE) + kk * 16 + k_koff) * 2;
                ldsm_x4(b0a, b1a, b0b, b1b, addr);
                mma_f16(sacc[2 * jp],     qf[kk][0], qf[kk][1], qf[kk][2], qf[kk][3], b0a, b1a);
                mma_f16(sacc[2 * jp + 1], qf[kk][0], qf[kk][1], qf[kk][2], qf[kk][3], b0b, b1b);
            }
        }

        // online softmax in exp2 domain
        float mx0 = -INFINITY, mx1 = -INFINITY;
        #pragma unroll
        for (int j = 0; j < 8; j++) {
            mx0 = fmaxf(mx0, fmaxf(sacc[j][0], sacc[j][1]));
            mx1 = fmaxf(mx1, fmaxf(sacc[j][2], sacc[j][3]));
        }
        #pragma unroll
        for (int off = 1; off <= 2; off <<= 1) {
            mx0 = fmaxf(mx0, __shfl_xor_sync(0xffffffffu, mx0, off));
            mx1 = fmaxf(mx1, __shfl_xor_sync(0xffffffffu, mx1, off));
        }
        const float mn0 = fmaxf(m0, mx0);
        const float mn1 = fmaxf(m1, mx1);
        const float corr0 = exp2f(m0 - mn0);
        const float corr1 = exp2f(m1 - mn1);
        m0 = mn0; m1 = mn1;

        // P = 2^(s - mn) as packed halves (these are the PV A-frags)
        unsigned pa[8], pb[8];
        #pragma unroll
        for (int j = 0; j < 8; j++) {
            pa[j] = ex2_h2(pack_h2(sacc[j][0] - mn0, sacc[j][1] - mn0));
            pb[j] = ex2_h2(pack_h2(sacc[j][2] - mn1, sacc[j][3] - mn1));
        }

        // rescale accumulators
        #pragma unroll
        for (int j = 0; j < 8; j++) {
            oacc[j][0] *= corr0; oacc[j][1] *= corr0;
            oacc[j][2] *= corr1; oacc[j][3] *= corr1;
        }
        ol[0] *= corr0; ol[1] *= corr0; ol[2] *= corr1; ol[3] *= corr1;

        // O += P @ V ; l += P @ ones
        const unsigned vsbase = smem_u32(&Vs[buf][0]);
        #pragma unroll
        for (int kk = 0; kk < 4; kk++) {
            const unsigned a0 = pa[2 * kk];
            const unsigned a1 = pb[2 * kk];
            const unsigned a2 = pa[2 * kk + 1];
            const unsigned a3 = pb[2 * kk + 1];
            #pragma unroll
            for (int p = 0; p < 4; p++) {
                unsigned r0, r1, r2, r3;
                const unsigned addr = vsbase +
                    (((kk * 16 + v_row) * VS_STRIDE) + p * 16 + v_col) * 2;
                ldsm_x4_t(r0, r1, r2, r3, addr);
                mma_f16(oacc[2 * p],     a0, a1, a2, a3, r0, r1);
                mma_f16(oacc[2 * p + 1], a0, a1, a2, a3, r2, r3);
            }
            mma_f16(ol, a0, a1, a2, a3, ONE_H2, ONE_H2);
        }
    }

    // Final: normalize + store [B, S, D] fp32
    const float inv0 = 1.0f / ol[0];
    const float inv1 = 1.0f / ol[2];
    const int row0 = qt * QT_ROWS + wrp * 16 + g;
    const int row1 = row0 + 8;
    const size_t o0 = ((size_t)(b * S_ + row0)) * D_ + h * DH_;
    const size_t o1 = ((size_t)(b * S_ + row1)) * D_ + h * DH_;
    #pragma unroll
    for (int j = 0; j < 8; j++) {
        const int d = j * 8 + 2 * t;
        *reinterpret_cast<float2*>(&out[o0 + d]) =
            make_float2(oacc[j][0] * inv0, oacc[j][1] * inv0);
        *reinterpret_cast<float2*>(&out[o1 + d]) =
            make_float2(oacc[j][2] * inv1, oacc[j][3] * inv1);
    }
}

// ---------------------------------------------------------------------------
extern "C" void kernel_launch(void* const* d_in, const int* in_sizes, int n_in,
                              void* d_out, int out_size)
{
    const float* x  = (const float*)d_in[0];
    const float* Wq = (const float*)d_in[1];
    const float* bq = (const float*)d_in[2];
    const float* Wk = (const float*)d_in[3];
    const float* bk = (const float*)d_in[4];
    const float* Wv = (const float*)d_in[5];
    const float* bv = (const float*)d_in[6];
    float* out = (float*)d_out;

    cvt_x_kernel<<<1024, 256>>>(x);
    cvt_w_kernel<<<dim3(32, 32, 3), dim3(32, 8)>>>(Wq, Wk, Wv);

    const int gsm_bytes = 4 * G_BUF * sizeof(__half);
    cudaFuncSetAttribute(qkv_gemm_f16,
                         cudaFuncAttributeMaxDynamicSharedMemorySize, gsm_bytes);
    qkv_gemm_f16<<<dim3(D_ / 128, M_ / 128, 3), 256, gsm_bytes>>>(bq, bk, bv);

    attn_f16<<<dim3(S_ / QT_ROWS, H_, B_), 128>>>(out);
}

// round 13
// speedup vs baseline: 3.2823x; 1.0200x over previous
#include <cuda_runtime.h>
#include <cuda_fp16.h>
#include <cuda_bf16.h>
#include <math.h>

// Problem constants
#define B_  4
#define S_  2048
#define D_  1024
#define H_  16
#define DH_ 64
#define M_  (B_ * S_)

// Scratch (fp16): projections + converted inputs
__device__ __half g_Q[B_ * H_ * S_ * DH_];     // pre-scaled by 0.125*log2(e)
__device__ __half g_K[B_ * H_ * S_ * DH_];
__device__ __half g_V[B_ * H_ * S_ * DH_];
__device__ __half g_Xh[M_ * D_];               // X in fp16
__device__ __half g_WTh[3 * D_ * D_];          // W^T in fp16: [z][n][k]

// ---------------------------------------------------------------------------
// Helpers
// ---------------------------------------------------------------------------
__device__ __forceinline__ void mma_f16(float c[4],
                                        unsigned a0, unsigned a1, unsigned a2, unsigned a3,
                                        unsigned b0, unsigned b1) {
    asm volatile(
        "mma.sync.aligned.m16n8k16.row.col.f32.f16.f16.f32 "
        "{%0,%1,%2,%3}, {%4,%5,%6,%7}, {%8,%9}, {%0,%1,%2,%3};"
        : "+f"(c[0]), "+f"(c[1]), "+f"(c[2]), "+f"(c[3])
        : "r"(a0), "r"(a1), "r"(a2), "r"(a3), "r"(b0), "r"(b1));
}

__device__ __forceinline__ void ldsm_x4(unsigned& r0, unsigned& r1,
                                        unsigned& r2, unsigned& r3, unsigned addr) {
    asm volatile(
        "ldmatrix.sync.aligned.m8n8.x4.shared.b16 {%0,%1,%2,%3}, [%4];"
        : "=r"(r0), "=r"(r1), "=r"(r2), "=r"(r3) : "r"(addr));
}

__device__ __forceinline__ void ldsm_x4_t(unsigned& r0, unsigned& r1,
                                          unsigned& r2, unsigned& r3, unsigned addr) {
    asm volatile(
        "ldmatrix.sync.aligned.m8n8.x4.trans.shared.b16 {%0,%1,%2,%3}, [%4];"
        : "=r"(r0), "=r"(r1), "=r"(r2), "=r"(r3) : "r"(addr));
}

__device__ __forceinline__ unsigned smem_u32(const void* p) {
    unsigned a;
    asm("{ .reg .u64 t; cvta.to.shared.u64 t, %1; cvt.u32.u64 %0, t; }"
        : "=r"(a) : "l"(p));
    return a;
}

__device__ __forceinline__ void cp_async16(unsigned saddr, const void* gptr) {
    asm volatile("cp.async.cg.shared.global [%0], [%1], 16;"
                 :: "r"(saddr), "l"(gptr));
}
__device__ __forceinline__ void cp_commit() {
    asm volatile("cp.async.commit_group;");
}
__device__ __forceinline__ void cp_wait_all() {
    asm volatile("cp.async.wait_group 0;");
}

__device__ __forceinline__ unsigned ex2_h2(unsigned x) {
    unsigned d;
    asm("ex2.approx.f16x2 %0, %1;" : "=r"(d) : "r"(x));
    return d;
}

__device__ __forceinline__ unsigned pack_h2(float x, float y) {
    __half2 h = __floats2half2_rn(x, y);
    return *reinterpret_cast<unsigned*>(&h);
}

#define ONE_H2 0x3C003C00u   // half2(1.0, 1.0)

// ---------------------------------------------------------------------------
// Pre-pass A: X (fp32) -> g_Xh (fp16)
// ---------------------------------------------------------------------------
__global__ void cvt_x_kernel(const float* __restrict__ X)
{
    const int n4 = M_ * D_ / 4;
    for (int i = blockIdx.x * blockDim.x + threadIdx.x; i < n4;
         i += gridDim.x * blockDim.x) {
        float4 v = reinterpret_cast<const float4*>(X)[i];
        __half2 h0 = __floats2half2_rn(v.x, v.y);
        __half2 h1 = __floats2half2_rn(v.z, v.w);
        uint2 o;
        o.x = *reinterpret_cast<unsigned*>(&h0);
        o.y = *reinterpret_cast<unsigned*>(&h1);
        reinterpret_cast<uint2*>(g_Xh)[i] = o;
    }
}

// ---------------------------------------------------------------------------
// Pre-pass B: W (fp32 [K][N]) -> g_WTh (fp16 [N][K])
// ---------------------------------------------------------------------------
__global__ void cvt_w_kernel(const float* __restrict__ Wq,
                             const float* __restrict__ Wk,
                             const float* __restrict__ Wv)
{
    __shared__ float tile[32][33];
    const int z = blockIdx.z;
    const float* W = (z == 0) ? Wq : (z == 1) ? Wk : Wv;
    __half* WT = g_WTh + (size_t)z * D_ * D_;
    const int x0 = blockIdx.x * 32, y0 = blockIdx.y * 32;
    for (int dy = threadIdx.y; dy < 32; dy += 8)
        tile[dy][threadIdx.x] = W[(size_t)(y0 + dy) * D_ + x0 + threadIdx.x];
    __syncthreads();
    for (int dy = threadIdx.y; dy < 32; dy += 8)
        WT[(size_t)(x0 + dy) * D_ + y0 + threadIdx.x] = __float2half_rn(tile[threadIdx.x][dy]);
}

// ---------------------------------------------------------------------------
// Kernel 1: QKV projection GEMM, fp16 m16n8k16, fp32 accumulate.
// BM=128, BN=128, BK=64; 256 threads (8 warps, 2x4); warp tile 64x32.
// __launch_bounds__(256, 2): cap regs at 128 -> 2 CTAs/SM (148KB smem < 227).
// All smem LDSM/staging addresses hoisted to per-buffer base registers.
// ---------------------------------------------------------------------------
#define GS 72
#define G_BUF (128 * GS)

__global__ __launch_bounds__(256, 2)
void qkv_gemm_f16(const float* __restrict__ bq,
                  const float* __restrict__ bk,
                  const float* __restrict__ bv)
{
    extern __shared__ __half gsm[];

    const int tid  = threadIdx.x;
    const int lane = tid & 31;
    const int wrp  = tid >> 5;
    const int g    = lane >> 2;
    const int t    = lane & 3;
    const int wm   = wrp >> 2;
    const int wn   = wrp & 3;

    const int n0 = blockIdx.x * 128;
    const int m0 = blockIdx.y * 128;
    const int z  = blockIdx.z;

    const float* bias = (z == 0) ? bq : (z == 1) ? bk : bv;
    __half* dst       = (z == 0) ? g_Q : (z == 1) ? g_K : g_V;
    const float oscale = (z == 0) ? 0.125f * 1.4426950408889634f : 1.0f;
    const __half* Ah = g_Xh + (size_t)m0 * D_;
    const __half* Bh = g_WTh + (size_t)z * D_ * D_ + (size_t)n0 * D_;

    // smem bases (u32) for the 4 tensors (A0,B0,A1,B1)
    const unsigned smb = smem_u32(gsm);
    const unsigned As_b[2] = { smb,                          smb + 4u * G_BUF };
    const unsigned Bs_b[2] = { smb + 2u * G_BUF,             smb + 6u * G_BUF };

    // staging offsets (bytes), per-thread
    unsigned st_off[4];
    int sr[4], sc[4];
    #pragma unroll
    for (int it = 0; it < 4; it++) {
        const int idx = tid + it * 256;
        sr[it] = idx >> 3;
        sc[it] = (idx & 7) << 3;
        st_off[it] = (unsigned)(sr[it] * GS + sc[it]) * 2u;
    }

    // prologue: stage k-tile 0
    #pragma unroll
    for (int it = 0; it < 4; it++) {
        cp_async16(As_b[0] + st_off[it], &Ah[(size_t)sr[it] * D_ + sc[it]]);
        cp_async16(Bs_b[0] + st_off[it], &Bh[(size_t)sr[it] * D_ + sc[it]]);
    }
    cp_commit();

    float acc[4][4][4];
    #pragma unroll
    for (int i = 0; i < 4; i++)
        #pragma unroll
        for (int j = 0; j < 4; j++)
            #pragma unroll
            for (int r = 0; r < 4; r++) acc[i][j][r] = 0.0f;

    // hoisted fragment base addresses (per buffer)
    const int a_row = lane & 15;
    const int a_col = (lane >> 4) << 3;
    const unsigned a_fb[2] = {
        As_b[0] + (unsigned)((wm * 64 + a_row) * GS + a_col) * 2u,
        As_b[1] + (unsigned)((wm * 64 + a_row) * GS + a_col) * 2u };
    const unsigned b_fb[2] = {
        Bs_b[0] + (unsigned)((wn * 32 + g) * GS + 2 * t) * 2u,
        Bs_b[1] + (unsigned)((wn * 32 + g) * GS + 2 * t) * 2u };

    for (int kt = 0; kt < D_ / 64; kt++) {
        const int buf = kt & 1;
        cp_wait_all();
        __syncthreads();

        if (kt + 1 < D_ / 64) {
            const int nb = (kt + 1) & 1;
            const int k0 = (kt + 1) * 64;
            #pragma unroll
            for (int it = 0; it < 4; it++) {
                cp_async16(As_b[nb] + st_off[it], &Ah[(size_t)sr[it] * D_ + k0 + sc[it]]);
                cp_async16(Bs_b[nb] + st_off[it], &Bh[(size_t)sr[it] * D_ + k0 + sc[it]]);
            }
            cp_commit();
        }

        const unsigned afb = a_fb[buf];
        const unsigned bfb = b_fb[buf];
        #pragma unroll
        for (int kk = 0; kk < 4; kk++) {
            unsigned af[4][4];
            #pragma unroll
            for (int i = 0; i < 4; i++) {
                ldsm_x4(af[i][0], af[i][1], af[i][2], af[i][3],
                        afb + (unsigned)((i * 16 * GS + kk * 16) * 2));
            }
            unsigned bf[4][2];
            #pragma unroll
            for (int j = 0; j < 4; j++) {
                const unsigned boff = bfb + (unsigned)((j * 8 * GS + kk * 16) * 2);
                asm volatile("ld.shared.b32 %0, [%1];" : "=r"(bf[j][0]) : "r"(boff));
                asm volatile("ld.shared.b32 %0, [%1];" : "=r"(bf[j][1]) : "r"(boff + 16));
            }
            #pragma unroll
            for (int i = 0; i < 4; i++)
                #pragma unroll
                for (int j = 0; j < 4; j++)
                    mma_f16(acc[i][j], af[i][0], af[i][1], af[i][2], af[i][3],
                            bf[j][0], bf[j][1]);
        }
    }

    #pragma unroll
    for (int i = 0; i < 4; i++) {
        const int mrow0 = m0 + wm * 64 + i * 16 + g;
        const int mrow1 = mrow0 + 8;
        #pragma unroll
        for (int j = 0; j < 4; j++) {
            const int n = n0 + wn * 32 + j * 8 + 2 * t;
            const int h = n >> 6;
            const int d = n & 63;
            const float b0v = bias[n], b1v = bias[n + 1];
            {
                const int bb = mrow0 >> 11, s = mrow0 & 2047;
                __half2 v = __floats2half2_rn((acc[i][j][0] + b0v) * oscale,
                                              (acc[i][j][1] + b1v) * oscale);
                *reinterpret_cast<__half2*>(
                    &dst[(((size_t)(bb * H_ + h)) * S_ + s) * DH_ + d]) = v;
            }
            {
                const int bb = mrow1 >> 11, s = mrow1 & 2047;
                __half2 v = __floats2half2_rn((acc[i][j][2] + b0v) * oscale,
                                              (acc[i][j][3] + b1v) * oscale);
                *reinterpret_cast<__half2*>(
                    &dst[(((size_t)(bb * H_ + h)) * S_ + s) * DH_ + d]) = v;
            }
        }
    }
}

// ---------------------------------------------------------------------------
// Kernel 2: flash attention, fp16 m16n8k16, exp2-domain softmax.
// __launch_bounds__(128, 5): cap regs ~102 -> 5 CTAs/SM.
// LDSM + staging addresses hoisted to per-buffer base registers.
// ---------------------------------------------------------------------------
#define KS_STRIDE 72
#define VS_STRIDE 72
#define QT_ROWS 64

__global__ __launch_bounds__(128, 5)
void attn_f16(float* __restrict__ out)
{
    __shared__ __half Ks[2][64 * KS_STRIDE];
    __shared__ __half Vs[2][64 * VS_STRIDE];

    const int tid  = threadIdx.x;
    const int lane = tid & 31;
    const int wrp  = tid >> 5;
    const int g    = lane >> 2;
    const int t    = lane & 3;

    const int qt = blockIdx.x;
    const int h  = blockIdx.y;
    const int b  = blockIdx.z;

    const size_t head_base = ((size_t)(b * H_ + h)) * S_ * DH_;
    const __half* Qg = g_Q + head_base + (size_t)qt * QT_ROWS * DH_;
    const __half* Kg = g_K + head_base;
    const __half* Vg = g_V + head_base;

    // smem bases
    const unsigned ks_b[2] = { smem_u32(&Ks[0][0]), smem_u32(&Ks[1][0]) };
    const unsigned vs_b[2] = { smem_u32(&Vs[0][0]), smem_u32(&Vs[1][0]) };

    // staging offsets
    unsigned st_off[4];
    int cr[4], cc[4];
    #pragma unroll
    for (int it = 0; it < 4; it++) {
        const int idx = tid + it * 128;
        cr[it] = idx >> 3;
        cc[it] = (idx & 7) << 3;
        st_off[it] = (unsigned)(cr[it] * KS_STRIDE + cc[it]) * 2u;
    }

    #pragma unroll
    for (int it = 0; it < 4; it++) {
        cp_async16(ks_b[0] + st_off[it], &Kg[(size_t)cr[it] * DH_ + cc[it]]);
        cp_async16(vs_b[0] + st_off[it], &Vg[(size_t)cr[it] * DH_ + cc[it]]);
    }
    cp_commit();

    // Q fragments from gmem (pre-scaled by 0.125*log2e)
    unsigned qf[4][4];
    {
        const int r0 = wrp * 16 + g;
        #pragma unroll
        for (int kk = 0; kk < 4; kk++) {
            const int c = kk * 16 + 2 * t;
            qf[kk][0] = *reinterpret_cast<const unsigned*>(&Qg[(size_t)r0 * DH_ + c]);
            qf[kk][1] = *reinterpret_cast<const unsigned*>(&Qg[(size_t)(r0 + 8) * DH_ + c]);
            qf[kk][2] = *reinterpret_cast<const unsigned*>(&Qg[(size_t)r0 * DH_ + c + 8]);
            qf[kk][3] = *reinterpret_cast<const unsigned*>(&Qg[(size_t)(r0 + 8) * DH_ + c + 8]);
        }
    }

    // hoisted fragment base addresses (per buffer)
    const int v_row = (lane & 7) + ((lane >> 3) & 1) * 8;
    const int v_col = (lane >> 4) * 8;
    const int k_nrow = ((lane >> 4) << 3) + (lane & 7);
    const int k_koff = ((lane >> 3) & 1) * 8;
    const unsigned k_fb[2] = {
        ks_b[0] + (unsigned)(k_nrow * KS_STRIDE + k_koff) * 2u,
        ks_b[1] + (unsigned)(k_nrow * KS_STRIDE + k_koff) * 2u };
    const unsigned v_fb[2] = {
        vs_b[0] + (unsigned)(v_row * VS_STRIDE + v_col) * 2u,
        vs_b[1] + (unsigned)(v_row * VS_STRIDE + v_col) * 2u };

    float oacc[8][4];
    #pragma unroll
    for (int j = 0; j < 8; j++)
        #pragma unroll
        for (int r = 0; r < 4; r++) oacc[j][r] = 0.0f;
    float ol[4] = {0.0f, 0.0f, 0.0f, 0.0f};
    float m0 = -INFINITY, m1 = -INFINITY;

    for (int kt = 0; kt < S_ / 64; kt++) {
        const int buf = kt & 1;

        cp_wait_all();
        __syncthreads();

        if (kt + 1 < S_ / 64) {
            const int nb = (kt + 1) & 1;
            const size_t roff = (size_t)(kt + 1) * 64;
            #pragma unroll
            for (int it = 0; it < 4; it++) {
                cp_async16(ks_b[nb] + st_off[it], &Kg[(roff + cr[it]) * DH_ + cc[it]]);
                cp_async16(vs_b[nb] + st_off[it], &Vg[(roff + cr[it]) * DH_ + cc[it]]);
            }
            cp_commit();
        }

        // S = Q @ K^T (log2 domain); K frags via ldmatrix.x4
        float sacc[8][4];
        #pragma unroll
        for (int j = 0; j < 8; j++)
            #pragma unroll
            for (int r = 0; r < 4; r++) sacc[j][r] = 0.0f;

        const unsigned kfb = k_fb[buf];
        #pragma unroll
        for (int jp = 0; jp < 4; jp++) {
            #pragma unroll
            for (int kk = 0; kk < 4; kk++) {
                unsigned b0a, b1a, b0b, b1b;
                ldsm_x4(b0a, b1a, b0b, b1b,
                        kfb + (unsigned)((jp * 16 * KS_STRIDE + kk * 16) * 2));
                mma_f16(sacc[2 * jp],     qf[kk][0], qf[kk][1], qf[kk][2], qf[kk][3], b0a, b1a);
                mma_f16(sacc[2 * jp + 1], qf[kk][0], qf[kk][1], qf[kk][2], qf[kk][3], b0b, b1b);
            }
        }

        // online softmax in exp2 domain
        float mx0 = -INFINITY, mx1 = -INFINITY;
        #pragma unroll
        for (int j = 0; j < 8; j++) {
            mx0 = fmaxf(mx0, fmaxf(sacc[j][0], sacc[j][1]));
            mx1 = fmaxf(mx1, fmaxf(sacc[j][2], sacc[j][3]));
        }
        #pragma unroll
        for (int off = 1; off <= 2; off <<= 1) {
            mx0 = fmaxf(mx0, __shfl_xor_sync(0xffffffffu, mx0, off));
            mx1 = fmaxf(mx1, __shfl_xor_sync(0xffffffffu, mx1, off));
        }
        const float mn0 = fmaxf(m0, mx0);
        const float mn1 = fmaxf(m1, mx1);
        const float corr0 = exp2f(m0 - mn0);
        const float corr1 = exp2f(m1 - mn1);
        m0 = mn0; m1 = mn1;

        // P = 2^(s - mn) as packed halves (these are the PV A-frags)
        unsigned pa[8], pb[8];
        #pragma unroll
        for (int j = 0; j < 8; j++) {
            pa[j] = ex2_h2(pack_h2(sacc[j][0] - mn0, sacc[j][1] - mn0));
            pb[j] = ex2_h2(pack_h2(sacc[j][2] - mn1, sacc[j][3] - mn1));
        }

        // rescale accumulators
        #pragma unroll
        for (int j = 0; j < 8; j++) {
            oacc[j][0] *= corr0; oacc[j][1] *= corr0;
            oacc[j][2] *= corr1; oacc[j][3] *= corr1;
        }
        ol[0] *= corr0; ol[1] *= corr0; ol[2] *= corr1; ol[3] *= corr1;

        // O += P @ V ; l += P @ ones
        const unsigned vfb = v_fb[buf];
        #pragma unroll
        for (int kk = 0; kk < 4; kk++) {
            const unsigned a0 = pa[2 * kk];
            const unsigned a1 = pb[2 * kk];
            const unsigned a2 = pa[2 * kk + 1];
            const unsigned a3 = pb[2 * kk + 1];
            #pragma unroll
            for (int p = 0; p < 4; p++) {
                unsigned r0, r1, r2, r3;
                ldsm_x4_t(r0, r1, r2, r3,
                          vfb + (unsigned)((kk * 16 * VS_STRIDE + p * 16) * 2));
                mma_f16(oacc[2 * p],     a0, a1, a2, a3, r0, r1);
                mma_f16(oacc[2 * p + 1], a0, a1, a2, a3, r2, r3);
            }
            mma_f16(ol, a0, a1, a2, a3, ONE_H2, ONE_H2);
        }
    }

    // Final: normalize + store [B, S, D] fp32
    const float inv0 = 1.0f / ol[0];
    const float inv1 = 1.0f / ol[2];
    const int row0 = qt * QT_ROWS + wrp * 16 + g;
    const int row1 = row0 + 8;
    const size_t o0 = ((size_t)(b * S_ + row0)) * D_ + h * DH_;
    const size_t o1 = ((size_t)(b * S_ + row1)) * D_ + h * DH_;
    #pragma unroll
    for (int j = 0; j < 8; j++) {
        const int d = j * 8 + 2 * t;
        *reinterpret_cast<float2*>(&out[o0 + d]) =
            make_float2(oacc[j][0] * inv0, oacc[j][1] * inv0);
        *reinterpret_cast<float2*>(&out[o1 + d]) =
            make_float2(oacc[j][2] * inv1, oacc[j][3] * inv1);
    }
}

// ---------------------------------------------------------------------------
extern "C" void kernel_launch(void* const* d_in, const int* in_sizes, int n_in,
                              void* d_out, int out_size)
{
    const float* x  = (const float*)d_in[0];
    const float* Wq = (const float*)d_in[1];
    const float* bq = (const float*)d_in[2];
    const float* Wk = (const float*)d_in[3];
    const float* bk = (const float*)d_in[4];
    const float* Wv = (const float*)d_in[5];
    const float* bv = (const float*)d_in[6];
    float* out = (float*)d_out;

    cvt_x_kernel<<<1024, 256>>>(x);
    cvt_w_kernel<<<dim3(32, 32, 3), dim3(32, 8)>>>(Wq, Wk, Wv);

    const int gsm_bytes = 8 * G_BUF * sizeof(__half);
    cudaFuncSetAttribute(qkv_gemm_f16,
                         cudaFuncAttributeMaxDynamicSharedMemorySize, gsm_bytes);
    qkv_gemm_f16<<<dim3(D_ / 128, M_ / 128, 3), 256, gsm_bytes>>>(bq, bk, bv);

    attn_f16<<<dim3(S_ / QT_ROWS, H_, B_), 128>>>(out);
}

// round 14
// speedup vs baseline: 3.6796x; 1.1210x over previous
#include <cuda_runtime.h>
#include <cuda_fp16.h>
#include <cuda_bf16.h>
#include <math.h>

// Problem constants
#define B_  4
#define S_  2048
#define D_  1024
#define H_  16
#define DH_ 64
#define M_  (B_ * S_)

// Scratch (fp16): projections + converted inputs
__device__ __half g_Q[B_ * H_ * S_ * DH_];     // pre-scaled by 0.125*log2(e)
__device__ __half g_K[B_ * H_ * S_ * DH_];
__device__ __half g_V[B_ * H_ * S_ * DH_];
__device__ __half g_Xh[M_ * D_];               // X in fp16
__device__ __half g_WTh[3 * D_ * D_];          // W^T in fp16: [z][n][k]

// ---------------------------------------------------------------------------
// Helpers
// ---------------------------------------------------------------------------
__device__ __forceinline__ void mma_f16(float c[4],
                                        unsigned a0, unsigned a1, unsigned a2, unsigned a3,
                                        unsigned b0, unsigned b1) {
    asm volatile(
        "mma.sync.aligned.m16n8k16.row.col.f32.f16.f16.f32 "
        "{%0,%1,%2,%3}, {%4,%5,%6,%7}, {%8,%9}, {%0,%1,%2,%3};"
        : "+f"(c[0]), "+f"(c[1]), "+f"(c[2]), "+f"(c[3])
        : "r"(a0), "r"(a1), "r"(a2), "r"(a3), "r"(b0), "r"(b1));
}

__device__ __forceinline__ void ldsm_x4(unsigned& r0, unsigned& r1,
                                        unsigned& r2, unsigned& r3, unsigned addr) {
    asm volatile(
        "ldmatrix.sync.aligned.m8n8.x4.shared.b16 {%0,%1,%2,%3}, [%4];"
        : "=r"(r0), "=r"(r1), "=r"(r2), "=r"(r3) : "r"(addr));
}

__device__ __forceinline__ void ldsm_x4_t(unsigned& r0, unsigned& r1,
                                          unsigned& r2, unsigned& r3, unsigned addr) {
    asm volatile(
        "ldmatrix.sync.aligned.m8n8.x4.trans.shared.b16 {%0,%1,%2,%3}, [%4];"
        : "=r"(r0), "=r"(r1), "=r"(r2), "=r"(r3) : "r"(addr));
}

__device__ __forceinline__ unsigned smem_u32(const void* p) {
    unsigned a;
    asm("{ .reg .u64 t; cvta.to.shared.u64 t, %1; cvt.u32.u64 %0, t; }"
        : "=r"(a) : "l"(p));
    return a;
}

__device__ __forceinline__ void cp_async16(unsigned saddr, const void* gptr) {
    asm volatile("cp.async.cg.shared.global [%0], [%1], 16;"
                 :: "r"(saddr), "l"(gptr));
}
__device__ __forceinline__ void cp_commit() {
    asm volatile("cp.async.commit_group;");
}
__device__ __forceinline__ void cp_wait_all() {
    asm volatile("cp.async.wait_group 0;");
}
__device__ __forceinline__ void cp_wait_1() {
    asm volatile("cp.async.wait_group 1;");
}

__device__ __forceinline__ unsigned ex2_h2(unsigned x) {
    unsigned d;
    asm("ex2.approx.f16x2 %0, %1;" : "=r"(d) : "r"(x));
    return d;
}

__device__ __forceinline__ unsigned pack_h2(float x, float y) {
    __half2 h = __floats2half2_rn(x, y);
    return *reinterpret_cast<unsigned*>(&h);
}

#define ONE_H2 0x3C003C00u   // half2(1.0, 1.0)

// ---------------------------------------------------------------------------
// Merged pre-pass: z=0 -> X fp16; z=1..3 -> W^T fp16
// grid (32, 32, 4), block (32, 8)
// ---------------------------------------------------------------------------
__global__ void cvt_all_kernel(const float* __restrict__ X,
                               const float* __restrict__ Wq,
                               const float* __restrict__ Wk,
                               const float* __restrict__ Wv)
{
    const int z = blockIdx.z;
    if (z == 0) {
        const int bid = blockIdx.y * 32 + blockIdx.x;       // 0..1023
        const int tid = threadIdx.y * 32 + threadIdx.x;     // 0..255
        const int base = bid * 2048;                        // float4 units
        #pragma unroll
        for (int i = 0; i < 8; i++) {
            const int idx = base + i * 256 + tid;
            float4 v = reinterpret_cast<const float4*>(X)[idx];
            __half2 h0 = __floats2half2_rn(v.x, v.y);
            __half2 h1 = __floats2half2_rn(v.z, v.w);
            uint2 o;
            o.x = *reinterpret_cast<unsigned*>(&h0);
            o.y = *reinterpret_cast<unsigned*>(&h1);
            reinterpret_cast<uint2*>(g_Xh)[idx] = o;
        }
    } else {
        __shared__ float tile[32][33];
        const float* W = (z == 1) ? Wq : (z == 2) ? Wk : Wv;
        __half* WT = g_WTh + (size_t)(z - 1) * D_ * D_;
        const int x0 = blockIdx.x * 32, y0 = blockIdx.y * 32;
        for (int dy = threadIdx.y; dy < 32; dy += 8)
            tile[dy][threadIdx.x] = W[(size_t)(y0 + dy) * D_ + x0 + threadIdx.x];
        __syncthreads();
        for (int dy = threadIdx.y; dy < 32; dy += 8)
            WT[(size_t)(x0 + dy) * D_ + y0 + threadIdx.x] =
                __float2half_rn(tile[threadIdx.x][dy]);
    }
}

// ---------------------------------------------------------------------------
// Kernel 1: QKV projection GEMM, fp16 m16n8k16, fp32 accumulate.
// BM=128, BN=128, BK=64; 256 threads (8 warps, 2x4); warp tile 64x32.
// 3-stage cp.async pipeline (wait_group 1); A and B frags via ldmatrix.x4.
// __launch_bounds__(256, 2): 2 CTAs/SM (2 x 110.6KB smem = 221KB < 227).
// ---------------------------------------------------------------------------
#define GS 72
#define G_BUF (128 * GS)                 // halves per tensor per stage
#define G_STAGE_BYTES (2 * G_BUF * 2)    // A + B, bytes

__global__ __launch_bounds__(256, 2)
void qkv_gemm_f16(const float* __restrict__ bq,
                  const float* __restrict__ bk,
                  const float* __restrict__ bv)
{
    extern __shared__ __half gsm[];

    const int tid  = threadIdx.x;
    const int lane = tid & 31;
    const int wrp  = tid >> 5;
    const int g    = lane >> 2;
    const int t    = lane & 3;
    const int wm   = wrp >> 2;
    const int wn   = wrp & 3;

    const int n0 = blockIdx.x * 128;
    const int m0 = blockIdx.y * 128;
    const int z  = blockIdx.z;

    const float* bias = (z == 0) ? bq : (z == 1) ? bk : bv;
    __half* dst       = (z == 0) ? g_Q : (z == 1) ? g_K : g_V;
    const float oscale = (z == 0) ? 0.125f * 1.4426950408889634f : 1.0f;
    const __half* Ah = g_Xh + (size_t)m0 * D_;
    const __half* Bh = g_WTh + (size_t)z * D_ * D_ + (size_t)n0 * D_;

    // stage bases (bytes)
    const unsigned smb = smem_u32(gsm);
    unsigned As_b[3], Bs_b[3];
    #pragma unroll
    for (int s = 0; s < 3; s++) {
        As_b[s] = smb + (unsigned)s * G_STAGE_BYTES;
        Bs_b[s] = As_b[s] + (unsigned)(G_BUF * 2);
    }

    // staging offsets (bytes), per-thread
    unsigned st_off[4];
    int sr[4], sc[4];
    #pragma unroll
    for (int it = 0; it < 4; it++) {
        const int idx = tid + it * 256;
        sr[it] = idx >> 3;
        sc[it] = (idx & 7) << 3;
        st_off[it] = (unsigned)(sr[it] * GS + sc[it]) * 2u;
    }

    // prologue: stage k-tiles 0 and 1
    #pragma unroll
    for (int s = 0; s < 2; s++) {
        const int k0 = s * 64;
        #pragma unroll
        for (int it = 0; it < 4; it++) {
            cp_async16(As_b[s] + st_off[it], &Ah[(size_t)sr[it] * D_ + k0 + sc[it]]);
            cp_async16(Bs_b[s] + st_off[it], &Bh[(size_t)sr[it] * D_ + k0 + sc[it]]);
        }
        cp_commit();
    }

    float acc[4][4][4];
    #pragma unroll
    for (int i = 0; i < 4; i++)
        #pragma unroll
        for (int j = 0; j < 4; j++)
            #pragma unroll
            for (int r = 0; r < 4; r++) acc[i][j][r] = 0.0f;

    // hoisted fragment base addresses (per stage)
    const int a_row = lane & 15;
    const int a_col = (lane >> 4) << 3;
    const int b_nrow = ((lane >> 4) << 3) + (lane & 7);   // non-trans ldsm rows
    const int b_koff = ((lane >> 3) & 1) * 8;
    unsigned a_fb[3], b_fb[3];
    #pragma unroll
    for (int s = 0; s < 3; s++) {
        a_fb[s] = As_b[s] + (unsigned)((wm * 64 + a_row) * GS + a_col) * 2u;
        b_fb[s] = Bs_b[s] + (unsigned)((wn * 32 + b_nrow) * GS + b_koff) * 2u;
    }

    for (int kt = 0; kt < D_ / 64; kt++) {
        const int buf = kt % 3;
        cp_wait_1();          // stage kt complete (kt+1 may still be in flight)
        __syncthreads();

        // stage kt+2 (always commit to keep group accounting uniform)
        if (kt + 2 < D_ / 64) {
            const int nb = (kt + 2) % 3;
            const int k0 = (kt + 2) * 64;
            #pragma unroll
            for (int it = 0; it < 4; it++) {
                cp_async16(As_b[nb] + st_off[it], &Ah[(size_t)sr[it] * D_ + k0 + sc[it]]);
                cp_async16(Bs_b[nb] + st_off[it], &Bh[(size_t)sr[it] * D_ + k0 + sc[it]]);
            }
        }
        cp_commit();

        const unsigned afb = a_fb[buf];
        const unsigned bfb = b_fb[buf];
        #pragma unroll
        for (int kk = 0; kk < 4; kk++) {
            unsigned af[4][4];
            #pragma unroll
            for (int i = 0; i < 4; i++) {
                ldsm_x4(af[i][0], af[i][1], af[i][2], af[i][3],
                        afb + (unsigned)((i * 16 * GS + kk * 16) * 2));
            }
            // B frags via ldmatrix.x4: one per n16, pairs (r0,r1)/(r2,r3) per n8
            unsigned bf[4][2];
            {
                unsigned b0, b1, b2, b3;
                ldsm_x4(b0, b1, b2, b3, bfb + (unsigned)(kk * 32));
                bf[0][0] = b0; bf[0][1] = b1; bf[1][0] = b2; bf[1][1] = b3;
                ldsm_x4(b0, b1, b2, b3,
                        bfb + (unsigned)(16 * GS * 2 + kk * 32));
                bf[2][0] = b0; bf[2][1] = b1; bf[3][0] = b2; bf[3][1] = b3;
            }
            #pragma unroll
            for (int i = 0; i < 4; i++)
                #pragma unroll
                for (int j = 0; j < 4; j++)
                    mma_f16(acc[i][j], af[i][0], af[i][1], af[i][2], af[i][3],
                            bf[j][0], bf[j][1]);
        }
    }

    #pragma unroll
    for (int i = 0; i < 4; i++) {
        const int mrow0 = m0 + wm * 64 + i * 16 + g;
        const int mrow1 = mrow0 + 8;
        #pragma unroll
        for (int j = 0; j < 4; j++) {
            const int n = n0 + wn * 32 + j * 8 + 2 * t;
            const int h = n >> 6;
            const int d = n & 63;
            const float b0v = bias[n], b1v = bias[n + 1];
            {
                const int bb = mrow0 >> 11, s = mrow0 & 2047;
                __half2 v = __floats2half2_rn((acc[i][j][0] + b0v) * oscale,
                                              (acc[i][j][1] + b1v) * oscale);
                *reinterpret_cast<__half2*>(
                    &dst[(((size_t)(bb * H_ + h)) * S_ + s) * DH_ + d]) = v;
            }
            {
                const int bb = mrow1 >> 11, s = mrow1 & 2047;
                __half2 v = __floats2half2_rn((acc[i][j][2] + b0v) * oscale,
                                              (acc[i][j][3] + b1v) * oscale);
                *reinterpret_cast<__half2*>(
                    &dst[(((size_t)(bb * H_ + h)) * S_ + s) * DH_ + d]) = v;
            }
        }
    }
}

// ---------------------------------------------------------------------------
// Kernel 2: flash attention, fp16 m16n8k16, exp2-domain softmax (R13 best).
// ---------------------------------------------------------------------------
#define KS_STRIDE 72
#define VS_STRIDE 72
#define QT_ROWS 64

__global__ __launch_bounds__(128, 5)
void attn_f16(float* __restrict__ out)
{
    __shared__ __half Ks[2][64 * KS_STRIDE];
    __shared__ __half Vs[2][64 * VS_STRIDE];

    const int tid  = threadIdx.x;
    const int lane = tid & 31;
    const int wrp  = tid >> 5;
    const int g    = lane >> 2;
    const int t    = lane & 3;

    const int qt = blockIdx.x;
    const int h  = blockIdx.y;
    const int b  = blockIdx.z;

    const size_t head_base = ((size_t)(b * H_ + h)) * S_ * DH_;
    const __half* Qg = g_Q + head_base + (size_t)qt * QT_ROWS * DH_;
    const __half* Kg = g_K + head_base;
    const __half* Vg = g_V + head_base;

    const unsigned ks_b[2] = { smem_u32(&Ks[0][0]), smem_u32(&Ks[1][0]) };
    const unsigned vs_b[2] = { smem_u32(&Vs[0][0]), smem_u32(&Vs[1][0]) };

    unsigned st_off[4];
    int cr[4], cc[4];
    #pragma unroll
    for (int it = 0; it < 4; it++) {
        const int idx = tid + it * 128;
        cr[it] = idx >> 3;
        cc[it] = (idx & 7) << 3;
        st_off[it] = (unsigned)(cr[it] * KS_STRIDE + cc[it]) * 2u;
    }

    #pragma unroll
    for (int it = 0; it < 4; it++) {
        cp_async16(ks_b[0] + st_off[it], &Kg[(size_t)cr[it] * DH_ + cc[it]]);
        cp_async16(vs_b[0] + st_off[it], &Vg[(size_t)cr[it] * DH_ + cc[it]]);
    }
    cp_commit();

    unsigned qf[4][4];
    {
        const int r0 = wrp * 16 + g;
        #pragma unroll
        for (int kk = 0; kk < 4; kk++) {
            const int c = kk * 16 + 2 * t;
            qf[kk][0] = *reinterpret_cast<const unsigned*>(&Qg[(size_t)r0 * DH_ + c]);
            qf[kk][1] = *reinterpret_cast<const unsigned*>(&Qg[(size_t)(r0 + 8) * DH_ + c]);
            qf[kk][2] = *reinterpret_cast<const unsigned*>(&Qg[(size_t)r0 * DH_ + c + 8]);
            qf[kk][3] = *reinterpret_cast<const unsigned*>(&Qg[(size_t)(r0 + 8) * DH_ + c + 8]);
        }
    }

    const int v_row = (lane & 7) + ((lane >> 3) & 1) * 8;
    const int v_col = (lane >> 4) * 8;
    const int k_nrow = ((lane >> 4) << 3) + (lane & 7);
    const int k_koff = ((lane >> 3) & 1) * 8;
    const unsigned k_fb[2] = {
        ks_b[0] + (unsigned)(k_nrow * KS_STRIDE + k_koff) * 2u,
        ks_b[1] + (unsigned)(k_nrow * KS_STRIDE + k_koff) * 2u };
    const unsigned v_fb[2] = {
        vs_b[0] + (unsigned)(v_row * VS_STRIDE + v_col) * 2u,
        vs_b[1] + (unsigned)(v_row * VS_STRIDE + v_col) * 2u };

    float oacc[8][4];
    #pragma unroll
    for (int j = 0; j < 8; j++)
        #pragma unroll
        for (int r = 0; r < 4; r++) oacc[j][r] = 0.0f;
    float ol[4] = {0.0f, 0.0f, 0.0f, 0.0f};
    float m0 = -INFINITY, m1 = -INFINITY;

    for (int kt = 0; kt < S_ / 64; kt++) {
        const int buf = kt & 1;

        cp_wait_all();
        __syncthreads();

        if (kt + 1 < S_ / 64) {
            const int nb = (kt + 1) & 1;
            const size_t roff = (size_t)(kt + 1) * 64;
            #pragma unroll
            for (int it = 0; it < 4; it++) {
                cp_async16(ks_b[nb] + st_off[it], &Kg[(roff + cr[it]) * DH_ + cc[it]]);
                cp_async16(vs_b[nb] + st_off[it], &Vg[(roff + cr[it]) * DH_ + cc[it]]);
            }
            cp_commit();
        }

        float sacc[8][4];
        #pragma unroll
        for (int j = 0; j < 8; j++)
            #pragma unroll
            for (int r = 0; r < 4; r++) sacc[j][r] = 0.0f;

        const unsigned kfb = k_fb[buf];
        #pragma unroll
        for (int jp = 0; jp < 4; jp++) {
            #pragma unroll
            for (int kk = 0; kk < 4; kk++) {
                unsigned b0a, b1a, b0b, b1b;
                ldsm_x4(b0a, b1a, b0b, b1b,
                        kfb + (unsigned)((jp * 16 * KS_STRIDE + kk * 16) * 2));
                mma_f16(sacc[2 * jp],     qf[kk][0], qf[kk][1], qf[kk][2], qf[kk][3], b0a, b1a);
                mma_f16(sacc[2 * jp + 1], qf[kk][0], qf[kk][1], qf[kk][2], qf[kk][3], b0b, b1b);
            }
        }

        float mx0 = -INFINITY, mx1 = -INFINITY;
        #pragma unroll
        for (int j = 0; j < 8; j++) {
            mx0 = fmaxf(mx0, fmaxf(sacc[j][0], sacc[j][1]));
            mx1 = fmaxf(mx1, fmaxf(sacc[j][2], sacc[j][3]));
        }
        #pragma unroll
        for (int off = 1; off <= 2; off <<= 1) {
            mx0 = fmaxf(mx0, __shfl_xor_sync(0xffffffffu, mx0, off));
            mx1 = fmaxf(mx1, __shfl_xor_sync(0xffffffffu, mx1, off));
        }
        const float mn0 = fmaxf(m0, mx0);
        const float mn1 = fmaxf(m1, mx1);
        const float corr0 = exp2f(m0 - mn0);
        const float corr1 = exp2f(m1 - mn1);
        m0 = mn0; m1 = mn1;

        unsigned pa[8], pb[8];
        #pragma unroll
        for (int j = 0; j < 8; j++) {
            pa[j] = ex2_h2(pack_h2(sacc[j][0] - mn0, sacc[j][1] - mn0));
            pb[j] = ex2_h2(pack_h2(sacc[j][2] - mn1, sacc[j][3] - mn1));
        }

        #pragma unroll
        for (int j = 0; j < 8; j++) {
            oacc[j][0] *= corr0; oacc[j][1] *= corr0;
            oacc[j][2] *= corr1; oacc[j][3] *= corr1;
        }
        ol[0] *= corr0; ol[1] *= corr0; ol[2] *= corr1; ol[3] *= corr1;

        const unsigned vfb = v_fb[buf];
        #pragma unroll
        for (int kk = 0; kk < 4; kk++) {
            const unsigned a0 = pa[2 * kk];
            const unsigned a1 = pb[2 * kk];
            const unsigned a2 = pa[2 * kk + 1];
            const unsigned a3 = pb[2 * kk + 1];
            #pragma unroll
            for (int p = 0; p < 4; p++) {
                unsigned r0, r1, r2, r3;
                ldsm_x4_t(r0, r1, r2, r3,
                          vfb + (unsigned)((kk * 16 * VS_STRIDE + p * 16) * 2));
                mma_f16(oacc[2 * p],     a0, a1, a2, a3, r0, r1);
                mma_f16(oacc[2 * p + 1], a0, a1, a2, a3, r2, r3);
            }
            mma_f16(ol, a0, a1, a2, a3, ONE_H2, ONE_H2);
        }
    }

    const float inv0 = 1.0f / ol[0];
    const float inv1 = 1.0f / ol[2];
    const int row0 = qt * QT_ROWS + wrp * 16 + g;
    const int row1 = row0 + 8;
    const size_t o0 = ((size_t)(b * S_ + row0)) * D_ + h * DH_;
    const size_t o1 = ((size_t)(b * S_ + row1)) * D_ + h * DH_;
    #pragma unroll
    for (int j = 0; j < 8; j++) {
        const int d = j * 8 + 2 * t;
        *reinterpret_cast<float2*>(&out[o0 + d]) =
            make_float2(oacc[j][0] * inv0, oacc[j][1] * inv0);
        *reinterpret_cast<float2*>(&out[o1 + d]) =
            make_float2(oacc[j][2] * inv1, oacc[j][3] * inv1);
    }
}

// ---------------------------------------------------------------------------
extern "C" void kernel_launch(void* const* d_in, const int* in_sizes, int n_in,
                              void* d_out, int out_size)
{
    const float* x  = (const float*)d_in[0];
    const float* Wq = (const float*)d_in[1];
    const float* bq = (const float*)d_in[2];
    const float* Wk = (const float*)d_in[3];
    const float* bk = (const float*)d_in[4];
    const float* Wv = (const float*)d_in[5];
    const float* bv = (const float*)d_in[6];
    float* out = (float*)d_out;

    cvt_all_kernel<<<dim3(32, 32, 4), dim3(32, 8)>>>(x, Wq, Wk, Wv);

    const int gsm_bytes = 3 * G_STAGE_BYTES;
    cudaFuncSetAttribute(qkv_gemm_f16,
                         cudaFuncAttributeMaxDynamicSharedMemorySize, gsm_bytes);
    qkv_gemm_f16<<<dim3(D_ / 128, M_ / 128, 3), 256, gsm_bytes>>>(bq, bk, bv);

    attn_f16<<<dim3(S_ / QT_ROWS, H_, B_), 128>>>(out);
}

// round 15
// speedup vs baseline: 3.8636x; 1.0500x over previous
#include <cuda_runtime.h>
#include <cuda_fp16.h>
#include <cuda_bf16.h>
#include <math.h>

// Problem constants
#define B_  4
#define S_  2048
#define D_  1024
#define H_  16
#define DH_ 64
#define M_  (B_ * S_)

// Scratch (fp16): projections + converted inputs
__device__ __half g_Q[B_ * H_ * S_ * DH_];     // pre-scaled by 0.125*log2(e)
__device__ __half g_K[B_ * H_ * S_ * DH_];
__device__ __half g_V[B_ * H_ * S_ * DH_];
__device__ __half g_Xh[M_ * D_];               // X in fp16
__device__ __half g_WTh[3 * D_ * D_];          // W^T in fp16: [z][n][k]

// ---------------------------------------------------------------------------
// Helpers
// ---------------------------------------------------------------------------
__device__ __forceinline__ void mma_f16(float c[4],
                                        unsigned a0, unsigned a1, unsigned a2, unsigned a3,
                                        unsigned b0, unsigned b1) {
    asm volatile(
        "mma.sync.aligned.m16n8k16.row.col.f32.f16.f16.f32 "
        "{%0,%1,%2,%3}, {%4,%5,%6,%7}, {%8,%9}, {%0,%1,%2,%3};"
        : "+f"(c[0]), "+f"(c[1]), "+f"(c[2]), "+f"(c[3])
        : "r"(a0), "r"(a1), "r"(a2), "r"(a3), "r"(b0), "r"(b1));
}

__device__ __forceinline__ void ldsm_x4(unsigned& r0, unsigned& r1,
                                        unsigned& r2, unsigned& r3, unsigned addr) {
    asm volatile(
        "ldmatrix.sync.aligned.m8n8.x4.shared.b16 {%0,%1,%2,%3}, [%4];"
        : "=r"(r0), "=r"(r1), "=r"(r2), "=r"(r3) : "r"(addr));
}

__device__ __forceinline__ void ldsm_x4_t(unsigned& r0, unsigned& r1,
                                          unsigned& r2, unsigned& r3, unsigned addr) {
    asm volatile(
        "ldmatrix.sync.aligned.m8n8.x4.trans.shared.b16 {%0,%1,%2,%3}, [%4];"
        : "=r"(r0), "=r"(r1), "=r"(r2), "=r"(r3) : "r"(addr));
}

__device__ __forceinline__ unsigned smem_u32(const void* p) {
    unsigned a;
    asm("{ .reg .u64 t; cvta.to.shared.u64 t, %1; cvt.u32.u64 %0, t; }"
        : "=r"(a) : "l"(p));
    return a;
}

__device__ __forceinline__ void cp_async16(unsigned saddr, const void* gptr) {
    asm volatile("cp.async.cg.shared.global [%0], [%1], 16;"
                 :: "r"(saddr), "l"(gptr));
}
__device__ __forceinline__ void cp_commit() {
    asm volatile("cp.async.commit_group;");
}
__device__ __forceinline__ void cp_wait_all() {
    asm volatile("cp.async.wait_group 0;");
}
__device__ __forceinline__ void cp_wait_1() {
    asm volatile("cp.async.wait_group 1;");
}

__device__ __forceinline__ unsigned ex2_h2(unsigned x) {
    unsigned d;
    asm("ex2.approx.f16x2 %0, %1;" : "=r"(d) : "r"(x));
    return d;
}

__device__ __forceinline__ unsigned pack_h2(float x, float y) {
    __half2 h = __floats2half2_rn(x, y);
    return *reinterpret_cast<unsigned*>(&h);
}

#define ONE_H2 0x3C003C00u   // half2(1.0, 1.0)

// ---------------------------------------------------------------------------
// Merged pre-pass: z=0 -> X fp16; z=1..3 -> W^T fp16
// ---------------------------------------------------------------------------
__global__ void cvt_all_kernel(const float* __restrict__ X,
                               const float* __restrict__ Wq,
                               const float* __restrict__ Wk,
                               const float* __restrict__ Wv)
{
    const int z = blockIdx.z;
    if (z == 0) {
        const int bid = blockIdx.y * 32 + blockIdx.x;
        const int tid = threadIdx.y * 32 + threadIdx.x;
        const int base = bid * 2048;
        #pragma unroll
        for (int i = 0; i < 8; i++) {
            const int idx = base + i * 256 + tid;
            float4 v = reinterpret_cast<const float4*>(X)[idx];
            __half2 h0 = __floats2half2_rn(v.x, v.y);
            __half2 h1 = __floats2half2_rn(v.z, v.w);
            uint2 o;
            o.x = *reinterpret_cast<unsigned*>(&h0);
            o.y = *reinterpret_cast<unsigned*>(&h1);
            reinterpret_cast<uint2*>(g_Xh)[idx] = o;
        }
    } else {
        __shared__ float tile[32][33];
        const float* W = (z == 1) ? Wq : (z == 2) ? Wk : Wv;
        __half* WT = g_WTh + (size_t)(z - 1) * D_ * D_;
        const int x0 = blockIdx.x * 32, y0 = blockIdx.y * 32;
        for (int dy = threadIdx.y; dy < 32; dy += 8)
            tile[dy][threadIdx.x] = W[(size_t)(y0 + dy) * D_ + x0 + threadIdx.x];
        __syncthreads();
        for (int dy = threadIdx.y; dy < 32; dy += 8)
            WT[(size_t)(x0 + dy) * D_ + y0 + threadIdx.x] =
                __float2half_rn(tile[threadIdx.x][dy]);
    }
}

// ---------------------------------------------------------------------------
// Kernel 1: QKV projection GEMM (unchanged from R14 best).
// ---------------------------------------------------------------------------
#define GS 72
#define G_BUF (128 * GS)
#define G_STAGE_BYTES (2 * G_BUF * 2)

__global__ __launch_bounds__(256, 2)
void qkv_gemm_f16(const float* __restrict__ bq,
                  const float* __restrict__ bk,
                  const float* __restrict__ bv)
{
    extern __shared__ __half gsm[];

    const int tid  = threadIdx.x;
    const int lane = tid & 31;
    const int wrp  = tid >> 5;
    const int g    = lane >> 2;
    const int t    = lane & 3;
    const int wm   = wrp >> 2;
    const int wn   = wrp & 3;

    const int n0 = blockIdx.x * 128;
    const int m0 = blockIdx.y * 128;
    const int z  = blockIdx.z;

    const float* bias = (z == 0) ? bq : (z == 1) ? bk : bv;
    __half* dst       = (z == 0) ? g_Q : (z == 1) ? g_K : g_V;
    const float oscale = (z == 0) ? 0.125f * 1.4426950408889634f : 1.0f;
    const __half* Ah = g_Xh + (size_t)m0 * D_;
    const __half* Bh = g_WTh + (size_t)z * D_ * D_ + (size_t)n0 * D_;

    const unsigned smb = smem_u32(gsm);
    unsigned As_b[3], Bs_b[3];
    #pragma unroll
    for (int s = 0; s < 3; s++) {
        As_b[s] = smb + (unsigned)s * G_STAGE_BYTES;
        Bs_b[s] = As_b[s] + (unsigned)(G_BUF * 2);
    }

    unsigned st_off[4];
    int sr[4], sc[4];
    #pragma unroll
    for (int it = 0; it < 4; it++) {
        const int idx = tid + it * 256;
        sr[it] = idx >> 3;
        sc[it] = (idx & 7) << 3;
        st_off[it] = (unsigned)(sr[it] * GS + sc[it]) * 2u;
    }

    #pragma unroll
    for (int s = 0; s < 2; s++) {
        const int k0 = s * 64;
        #pragma unroll
        for (int it = 0; it < 4; it++) {
            cp_async16(As_b[s] + st_off[it], &Ah[(size_t)sr[it] * D_ + k0 + sc[it]]);
            cp_async16(Bs_b[s] + st_off[it], &Bh[(size_t)sr[it] * D_ + k0 + sc[it]]);
        }
        cp_commit();
    }

    float acc[4][4][4];
    #pragma unroll
    for (int i = 0; i < 4; i++)
        #pragma unroll
        for (int j = 0; j < 4; j++)
            #pragma unroll
            for (int r = 0; r < 4; r++) acc[i][j][r] = 0.0f;

    const int a_row = lane & 15;
    const int a_col = (lane >> 4) << 3;
    const int b_nrow = ((lane >> 4) << 3) + (lane & 7);
    const int b_koff = ((lane >> 3) & 1) * 8;
    unsigned a_fb[3], b_fb[3];
    #pragma unroll
    for (int s = 0; s < 3; s++) {
        a_fb[s] = As_b[s] + (unsigned)((wm * 64 + a_row) * GS + a_col) * 2u;
        b_fb[s] = Bs_b[s] + (unsigned)((wn * 32 + b_nrow) * GS + b_koff) * 2u;
    }

    for (int kt = 0; kt < D_ / 64; kt++) {
        const int buf = kt % 3;
        cp_wait_1();
        __syncthreads();

        if (kt + 2 < D_ / 64) {
            const int nb = (kt + 2) % 3;
            const int k0 = (kt + 2) * 64;
            #pragma unroll
            for (int it = 0; it < 4; it++) {
                cp_async16(As_b[nb] + st_off[it], &Ah[(size_t)sr[it] * D_ + k0 + sc[it]]);
                cp_async16(Bs_b[nb] + st_off[it], &Bh[(size_t)sr[it] * D_ + k0 + sc[it]]);
            }
        }
        cp_commit();

        const unsigned afb = a_fb[buf];
        const unsigned bfb = b_fb[buf];
        #pragma unroll
        for (int kk = 0; kk < 4; kk++) {
            unsigned af[4][4];
            #pragma unroll
            for (int i = 0; i < 4; i++) {
                ldsm_x4(af[i][0], af[i][1], af[i][2], af[i][3],
                        afb + (unsigned)((i * 16 * GS + kk * 16) * 2));
            }
            unsigned bf[4][2];
            {
                unsigned b0, b1, b2, b3;
                ldsm_x4(b0, b1, b2, b3, bfb + (unsigned)(kk * 32));
                bf[0][0] = b0; bf[0][1] = b1; bf[1][0] = b2; bf[1][1] = b3;
                ldsm_x4(b0, b1, b2, b3,
                        bfb + (unsigned)(16 * GS * 2 + kk * 32));
                bf[2][0] = b0; bf[2][1] = b1; bf[3][0] = b2; bf[3][1] = b3;
            }
            #pragma unroll
            for (int i = 0; i < 4; i++)
                #pragma unroll
                for (int j = 0; j < 4; j++)
                    mma_f16(acc[i][j], af[i][0], af[i][1], af[i][2], af[i][3],
                            bf[j][0], bf[j][1]);
        }
    }

    #pragma unroll
    for (int i = 0; i < 4; i++) {
        const int mrow0 = m0 + wm * 64 + i * 16 + g;
        const int mrow1 = mrow0 + 8;
        #pragma unroll
        for (int j = 0; j < 4; j++) {
            const int n = n0 + wn * 32 + j * 8 + 2 * t;
            const int h = n >> 6;
            const int d = n & 63;
            const float b0v = bias[n], b1v = bias[n + 1];
            {
                const int bb = mrow0 >> 11, s = mrow0 & 2047;
                __half2 v = __floats2half2_rn((acc[i][j][0] + b0v) * oscale,
                                              (acc[i][j][1] + b1v) * oscale);
                *reinterpret_cast<__half2*>(
                    &dst[(((size_t)(bb * H_ + h)) * S_ + s) * DH_ + d]) = v;
            }
            {
                const int bb = mrow1 >> 11, s = mrow1 & 2047;
                __half2 v = __floats2half2_rn((acc[i][j][2] + b0v) * oscale,
                                              (acc[i][j][3] + b1v) * oscale);
                *reinterpret_cast<__half2*>(
                    &dst[(((size_t)(bb * H_ + h)) * S_ + s) * DH_ + d]) = v;
            }
        }
    }
}

// ---------------------------------------------------------------------------
// Kernel 2: flash attention, fp16 m16n8k16, exp2-domain softmax,
// SOFTWARE-PIPELINED across tiles: PV(kt) interleaved with S(kt+1) in one
// 64-MMA block. 3 K/V buffers (dynamic smem 55.3KB), 4 CTAs/SM.
// ---------------------------------------------------------------------------
#define KS_STRIDE 72
#define VS_STRIDE 72
#define QT_ROWS 64
#define NT (S_ / 64)
#define K_BUF_BYTES (64 * KS_STRIDE * 2)
#define ATTN_SMEM_BYTES (6 * K_BUF_BYTES)

__global__ __launch_bounds__(128, 4)
void attn_f16(float* __restrict__ out)
{
    extern __shared__ __half asmem[];

    const int tid  = threadIdx.x;
    const int lane = tid & 31;
    const int wrp  = tid >> 5;
    const int g    = lane >> 2;
    const int t    = lane & 3;

    const int qt = blockIdx.x;
    const int h  = blockIdx.y;
    const int b  = blockIdx.z;

    const size_t head_base = ((size_t)(b * H_ + h)) * S_ * DH_;
    const __half* Qg = g_Q + head_base + (size_t)qt * QT_ROWS * DH_;
    const __half* Kg = g_K + head_base;
    const __half* Vg = g_V + head_base;

    const unsigned smb = smem_u32(asmem);
    unsigned ks_b[3], vs_b[3];
    #pragma unroll
    for (int s = 0; s < 3; s++) {
        ks_b[s] = smb + (unsigned)s * K_BUF_BYTES;
        vs_b[s] = smb + (unsigned)(3 + s) * K_BUF_BYTES;
    }

    unsigned st_off[4];
    int cr[4], cc[4];
    #pragma unroll
    for (int it = 0; it < 4; it++) {
        const int idx = tid + it * 128;
        cr[it] = idx >> 3;
        cc[it] = (idx & 7) << 3;
        st_off[it] = (unsigned)(cr[it] * KS_STRIDE + cc[it]) * 2u;
    }

    // stage tiles 0 and 1
    #pragma unroll
    for (int s = 0; s < 2; s++) {
        const size_t roff = (size_t)s * 64;
        #pragma unroll
        for (int it = 0; it < 4; it++) {
            cp_async16(ks_b[s] + st_off[it], &Kg[(roff + cr[it]) * DH_ + cc[it]]);
            cp_async16(vs_b[s] + st_off[it], &Vg[(roff + cr[it]) * DH_ + cc[it]]);
        }
    }
    cp_commit();

    // Q fragments from gmem (pre-scaled by 0.125*log2e)
    unsigned qf[4][4];
    {
        const int r0 = wrp * 16 + g;
        #pragma unroll
        for (int kk = 0; kk < 4; kk++) {
            const int c = kk * 16 + 2 * t;
            qf[kk][0] = *reinterpret_cast<const unsigned*>(&Qg[(size_t)r0 * DH_ + c]);
            qf[kk][1] = *reinterpret_cast<const unsigned*>(&Qg[(size_t)(r0 + 8) * DH_ + c]);
            qf[kk][2] = *reinterpret_cast<const unsigned*>(&Qg[(size_t)r0 * DH_ + c + 8]);
            qf[kk][3] = *reinterpret_cast<const unsigned*>(&Qg[(size_t)(r0 + 8) * DH_ + c + 8]);
        }
    }

    const int v_row = (lane & 7) + ((lane >> 3) & 1) * 8;
    const int v_col = (lane >> 4) * 8;
    const int k_nrow = ((lane >> 4) << 3) + (lane & 7);
    const int k_koff = ((lane >> 3) & 1) * 8;
    unsigned k_fb[3], v_fb[3];
    #pragma unroll
    for (int s = 0; s < 3; s++) {
        k_fb[s] = ks_b[s] + (unsigned)(k_nrow * KS_STRIDE + k_koff) * 2u;
        v_fb[s] = vs_b[s] + (unsigned)(v_row * VS_STRIDE + v_col) * 2u;
    }

    float oacc[8][4];
    #pragma unroll
    for (int j = 0; j < 8; j++)
        #pragma unroll
        for (int r = 0; r < 4; r++) oacc[j][r] = 0.0f;
    float ol[4] = {0.0f, 0.0f, 0.0f, 0.0f};
    float m0 = -INFINITY, m1 = -INFINITY;

    float sacc[8][4];
    #pragma unroll
    for (int j = 0; j < 8; j++)
        #pragma unroll
        for (int r = 0; r < 4; r++) sacc[j][r] = 0.0f;

    // prologue: S(0)
    cp_wait_all();
    __syncthreads();
    {
        const unsigned kfb = k_fb[0];
        #pragma unroll
        for (int jp = 0; jp < 4; jp++) {
            #pragma unroll
            for (int kk = 0; kk < 4; kk++) {
                unsigned b0a, b1a, b0b, b1b;
                ldsm_x4(b0a, b1a, b0b, b1b,
                        kfb + (unsigned)((jp * 16 * KS_STRIDE + kk * 16) * 2));
                mma_f16(sacc[2 * jp],     qf[kk][0], qf[kk][1], qf[kk][2], qf[kk][3], b0a, b1a);
                mma_f16(sacc[2 * jp + 1], qf[kk][0], qf[kk][1], qf[kk][2], qf[kk][3], b0b, b1b);
            }
        }
    }

    unsigned pa[8], pb[8];

    for (int kt = 0; kt < NT - 1; kt++) {
        // ---- softmax(kt) on sacc ----
        float mx0 = -INFINITY, mx1 = -INFINITY;
        #pragma unroll
        for (int j = 0; j < 8; j++) {
            mx0 = fmaxf(mx0, fmaxf(sacc[j][0], sacc[j][1]));
            mx1 = fmaxf(mx1, fmaxf(sacc[j][2], sacc[j][3]));
        }
        #pragma unroll
        for (int off = 1; off <= 2; off <<= 1) {
            mx0 = fmaxf(mx0, __shfl_xor_sync(0xffffffffu, mx0, off));
            mx1 = fmaxf(mx1, __shfl_xor_sync(0xffffffffu, mx1, off));
        }
        const float mn0 = fmaxf(m0, mx0);
        const float mn1 = fmaxf(m1, mx1);
        const float corr0 = exp2f(m0 - mn0);
        const float corr1 = exp2f(m1 - mn1);
        m0 = mn0; m1 = mn1;

        #pragma unroll
        for (int j = 0; j < 8; j++) {
            pa[j] = ex2_h2(pack_h2(sacc[j][0] - mn0, sacc[j][1] - mn0));
            pb[j] = ex2_h2(pack_h2(sacc[j][2] - mn1, sacc[j][3] - mn1));
        }
        #pragma unroll
        for (int j = 0; j < 8; j++) {
            oacc[j][0] *= corr0; oacc[j][1] *= corr0;
            oacc[j][2] *= corr1; oacc[j][3] *= corr1;
            sacc[j][0] = 0.0f; sacc[j][1] = 0.0f;
            sacc[j][2] = 0.0f; sacc[j][3] = 0.0f;
        }
        ol[0] *= corr0; ol[1] *= corr0; ol[2] *= corr1; ol[3] *= corr1;

        // ---- pipeline bookkeeping ----
        cp_wait_all();          // tile kt+1 fully arrived (each thread's groups)
        __syncthreads();        // visibility of all threads' copies; all warps past PV(kt-1)
        if (kt + 2 < NT) {
            const int sb = (kt + 2) % 3;
            const size_t roff = (size_t)(kt + 2) * 64;
            #pragma unroll
            for (int it = 0; it < 4; it++) {
                cp_async16(ks_b[sb] + st_off[it], &Kg[(roff + cr[it]) * DH_ + cc[it]]);
                cp_async16(vs_b[sb] + st_off[it], &Vg[(roff + cr[it]) * DH_ + cc[it]]);
            }
            cp_commit();
        }

        // ---- interleaved: PV(kt) + S(kt+1) ----
        const unsigned kfb = k_fb[(kt + 1) % 3];
        const unsigned vfb = v_fb[kt % 3];
        #pragma unroll
        for (int u = 0; u < 4; u++) {
            // S(kt+1), n-tile u
            #pragma unroll
            for (int kk = 0; kk < 4; kk++) {
                unsigned b0a, b1a, b0b, b1b;
                ldsm_x4(b0a, b1a, b0b, b1b,
                        kfb + (unsigned)((u * 16 * KS_STRIDE + kk * 16) * 2));
                mma_f16(sacc[2 * u],     qf[kk][0], qf[kk][1], qf[kk][2], qf[kk][3], b0a, b1a);
                mma_f16(sacc[2 * u + 1], qf[kk][0], qf[kk][1], qf[kk][2], qf[kk][3], b0b, b1b);
            }
            // PV(kt), d-tile u
            #pragma unroll
            for (int kk = 0; kk < 4; kk++) {
                unsigned r0, r1, r2, r3;
                ldsm_x4_t(r0, r1, r2, r3,
                          vfb + (unsigned)((kk * 16 * VS_STRIDE + u * 16) * 2));
                mma_f16(oacc[2 * u],     pa[2 * kk], pb[2 * kk], pa[2 * kk + 1], pb[2 * kk + 1], r0, r1);
                mma_f16(oacc[2 * u + 1], pa[2 * kk], pb[2 * kk], pa[2 * kk + 1], pb[2 * kk + 1], r2, r3);
            }
            // l += P@ones (one k-step per u)
            mma_f16(ol, pa[2 * u], pb[2 * u], pa[2 * u + 1], pb[2 * u + 1], ONE_H2, ONE_H2);
        }
    }

    // ---- final tile: softmax(NT-1) + PV only ----
    {
        float mx0 = -INFINITY, mx1 = -INFINITY;
        #pragma unroll
        for (int j = 0; j < 8; j++) {
            mx0 = fmaxf(mx0, fmaxf(sacc[j][0], sacc[j][1]));
            mx1 = fmaxf(mx1, fmaxf(sacc[j][2], sacc[j][3]));
        }
        #pragma unroll
        for (int off = 1; off <= 2; off <<= 1) {
            mx0 = fmaxf(mx0, __shfl_xor_sync(0xffffffffu, mx0, off));
            mx1 = fmaxf(mx1, __shfl_xor_sync(0xffffffffu, mx1, off));
        }
        const float mn0 = fmaxf(m0, mx0);
        const float mn1 = fmaxf(m1, mx1);
        const float corr0 = exp2f(m0 - mn0);
        const float corr1 = exp2f(m1 - mn1);

        #pragma unroll
        for (int j = 0; j < 8; j++) {
            pa[j] = ex2_h2(pack_h2(sacc[j][0] - mn0, sacc[j][1] - mn0));
            pb[j] = ex2_h2(pack_h2(sacc[j][2] - mn1, sacc[j][3] - mn1));
        }
        #pragma unroll
        for (int j = 0; j < 8; j++) {
            oacc[j][0] *= corr0; oacc[j][1] *= corr0;
            oacc[j][2] *= corr1; oacc[j][3] *= corr1;
        }
        ol[0] *= corr0; ol[1] *= corr0; ol[2] *= corr1; ol[3] *= corr1;

        const unsigned vfb = v_fb[(NT - 1) % 3];
        #pragma unroll
        for (int u = 0; u < 4; u++) {
            #pragma unroll
            for (int kk = 0; kk < 4; kk++) {
                unsigned r0, r1, r2, r3;
                ldsm_x4_t(r0, r1, r2, r3,
                          vfb + (unsigned)((kk * 16 * VS_STRIDE + u * 16) * 2));
                mma_f16(oacc[2 * u],     pa[2 * kk], pb[2 * kk], pa[2 * kk + 1], pb[2 * kk + 1], r0, r1);
                mma_f16(oacc[2 * u + 1], pa[2 * kk], pb[2 * kk], pa[2 * kk + 1], pb[2 * kk + 1], r2, r3);
            }
            mma_f16(ol, pa[2 * u], pb[2 * u], pa[2 * u + 1], pb[2 * u + 1], ONE_H2, ONE_H2);
        }
    }

    // Final: normalize + store [B, S, D] fp32
    const float inv0 = 1.0f / ol[0];
    const float inv1 = 1.0f / ol[2];
    const int row0 = qt * QT_ROWS + wrp * 16 + g;
    const int row1 = row0 + 8;
    const size_t o0 = ((size_t)(b * S_ + row0)) * D_ + h * DH_;
    const size_t o1 = ((size_t)(b * S_ + row1)) * D_ + h * DH_;
    #pragma unroll
    for (int j = 0; j < 8; j++) {
        const int d = j * 8 + 2 * t;
        *reinterpret_cast<float2*>(&out[o0 + d]) =
            make_float2(oacc[j][0] * inv0, oacc[j][1] * inv0);
        *reinterpret_cast<float2*>(&out[o1 + d]) =
            make_float2(oacc[j][2] * inv1, oacc[j][3] * inv1);
    }
}

// ---------------------------------------------------------------------------
extern "C" void kernel_launch(void* const* d_in, const int* in_sizes, int n_in,
                              void* d_out, int out_size)
{
    const float* x  = (const float*)d_in[0];
    const float* Wq = (const float*)d_in[1];
    const float* bq = (const float*)d_in[2];
    const float* Wk = (const float*)d_in[3];
    const float* bk = (const float*)d_in[4];
    const float* Wv = (const float*)d_in[5];
    const float* bv = (const float*)d_in[6];
    float* out = (float*)d_out;

    cvt_all_kernel<<<dim3(32, 32, 4), dim3(32, 8)>>>(x, Wq, Wk, Wv);

    const int gsm_bytes = 3 * G_STAGE_BYTES;
    cudaFuncSetAttribute(qkv_gemm_f16,
                         cudaFuncAttributeMaxDynamicSharedMemorySize, gsm_bytes);
    qkv_gemm_f16<<<dim3(D_ / 128, M_ / 128, 3), 256, gsm_bytes>>>(bq, bk, bv);

    cudaFuncSetAttribute(attn_f16,
                         cudaFuncAttributeMaxDynamicSharedMemorySize, ATTN_SMEM_BYTES);
    attn_f16<<<dim3(S_ / QT_ROWS, H_, B_), 128, ATTN_SMEM_BYTES>>>(out);
}